// round 8
// baseline (speedup 1.0000x reference)
#include <cuda_runtime.h>
#include <cuda_bf16.h>
#include <cstdint>

// ---------------- Problem constants ----------------
#define BATCH   2
#define LSEQ    2048
#define NTOK    (BATCH * LSEQ)      // 4096 tokens
#define DMODEL  1024
#define DINNER  2048
#define DSTATE  16
#define DCONV   4
#define DTRANK  64
#define NDBL    (DTRANK + 2 * DSTATE)   // 96
#define XP_SPLITS 8

// weight sizes (floats)
#define W_IN_SZ   ((size_t)2 * DINNER * DMODEL)   // 4,194,304
#define W_XP_SZ   ((size_t)NDBL * DINNER)         //   196,608
#define W_DT_SZ   ((size_t)DINNER * DTRANK)       //   131,072
#define W_OP_SZ   ((size_t)DMODEL * DINNER)       // 2,097,152

// ---------------- Scratch (device globals; no allocation allowed) ----------
#define OFF_H     ((size_t)0)
#define OFF_XZ    (OFF_H    + (size_t)NTOK * DMODEL)
#define OFF_XC    (OFF_XZ   + (size_t)NTOK * 2 * DINNER)
#define OFF_XDBL  (OFF_XC   + (size_t)NTOK * DINNER)
#define OFF_DT    (OFF_XDBL + (size_t)NTOK * NDBL)
#define OFF_Y     (OFF_DT   + (size_t)NTOK * DINNER)
#define OFF_XP    (OFF_Y    + (size_t)NTOK * DINNER)
#define OFF_WIN   (OFF_XP   + (size_t)XP_SPLITS * NTOK * NDBL)
#define OFF_WXP   (OFF_WIN  + W_IN_SZ)
#define OFF_WDT   (OFF_WXP  + W_XP_SZ)
#define OFF_WOP   (OFF_WDT  + W_DT_SZ)
#define SCRATCH_FLOATS (OFF_WOP + W_OP_SZ)

__device__ float g_scratch[SCRATCH_FLOATS];

// ---------------- helpers ----------------
__device__ __forceinline__ float siluf(float z) {
    return z * (1.0f / (1.0f + __expf(-z)));
}
__device__ __forceinline__ float softplusf(float v) {
    return fmaxf(v, 0.0f) + log1pf(expf(-fabsf(v)));
}

// k-permutation within each 32-wide block:
// original k = ks*8 + t4 + 4h  (ks 0..3, t4 0..3, h 0..1)
// position  p = t4*8 + ks*2 + h
__device__ __forceinline__ int perm32(int k) {
    return (k & 3) * 8 + (k >> 3) * 2 + ((k >> 2) & 1);
}

__device__ __forceinline__ uint32_t smem_u32(const void* p) {
    uint32_t addr;
    asm("{ .reg .u64 tmp; cvta.to.shared.u64 tmp, %1; cvt.u32.u64 %0, tmp; }"
        : "=r"(addr) : "l"(p));
    return addr;
}

__device__ __forceinline__ void cp16(uint32_t dst, const void* src) {
    asm volatile("cp.async.cg.shared.global [%0], [%1], 16;" :: "r"(dst), "l"(src));
}
__device__ __forceinline__ void cp_commit() {
    asm volatile("cp.async.commit_group;");
}
template <int N>
__device__ __forceinline__ void cp_wait() {
    asm volatile("cp.async.wait_group %0;" :: "n"(N));
}

__device__ __forceinline__ uint32_t to_tf32(float v) {
    uint32_t u;
    asm("cvt.rna.tf32.f32 %0, %1;" : "=r"(u) : "f"(v));
    return u;
}
__device__ __forceinline__ float round_tf32(float v) {
    return __uint_as_float(to_tf32(v));
}

__device__ __forceinline__ void mma_tf32(
    float& c0, float& c1, float& c2, float& c3,
    uint32_t a0, uint32_t a1, uint32_t a2, uint32_t a3,
    uint32_t b0, uint32_t b1)
{
    asm volatile(
        "mma.sync.aligned.m16n8k8.row.col.f32.tf32.tf32.f32 "
        "{%0,%1,%2,%3}, {%4,%5,%6,%7}, {%8,%9}, {%0,%1,%2,%3};"
        : "+f"(c0), "+f"(c1), "+f"(c2), "+f"(c3)
        : "r"(a0), "r"(a1), "r"(a2), "r"(a3), "r"(b0), "r"(b1));
}

// ------------- weight pre-round (natural order, for x_proj) ----------------
__global__ __launch_bounds__(256) void round_copy_kernel(
    const float4* __restrict__ in, float4* __restrict__ out, int n4)
{
    int i = blockIdx.x * blockDim.x + threadIdx.x;
    if (i >= n4) return;
    float4 v = in[i];
    v.x = round_tf32(v.x); v.y = round_tf32(v.y);
    v.z = round_tf32(v.z); v.w = round_tf32(v.w);
    out[i] = v;
}

// ------------- weight pre-round + k-permute (row length L, 32 | L) ---------
__global__ __launch_bounds__(256) void round_perm_kernel(
    const float4* __restrict__ in, float* __restrict__ out, int n4, int L)
{
    int i = blockIdx.x * blockDim.x + threadIdx.x;
    if (i >= n4) return;
    float4 v = in[i];
    int base = i * 4;
    int row = base / L;
    int col = base - row * L;
    int blk = col & ~31;
    int p = perm32(col & 31);
    float* orow = out + (size_t)row * L + blk;
    orow[p]      = round_tf32(v.x);
    orow[p + 8]  = round_tf32(v.y);
    orow[p + 16] = round_tf32(v.z);
    orow[p + 24] = round_tf32(v.w);
}

// ---------------- TF32 tensor-core GEMM: C[m,n] = sum_k A[m,k] * W[n,k] ----
#define SM_STRIDE 36
#define TILE_FLOATS (128 * SM_STRIDE)
#define BUF_BYTES  (TILE_FLOATS * 4)
#define MM_SMEM_BYTES (6 * BUF_BYTES)      // 110592 (3 stages x (A+B))

__device__ __forceinline__ void stage_tile(
    uint32_t sA, uint32_t sB,
    const float* __restrict__ A, int lda,
    const float* __restrict__ W, int ldw, int Nw,
    int m0, int n0, int k0, int tid)
{
    #pragma unroll
    for (int i = 0; i < 4; i++) {
        int idx = i * 256 + tid;
        int row = idx >> 3;
        int kc  = idx & 7;
        cp16(sA + (uint32_t)(row * SM_STRIDE + kc * 4) * 4,
             &A[(size_t)(m0 + row) * lda + k0 + kc * 4]);
    }
    #pragma unroll
    for (int i = 0; i < 4; i++) {
        int idx = i * 256 + tid;
        int row = idx >> 3;
        int kc  = idx & 7;
        int n = n0 + row;
        int nn = (n < Nw) ? n : 0;
        cp16(sB + (uint32_t)(row * SM_STRIDE + kc * 4) * 4,
             &W[(size_t)nn * ldw + k0 + kc * 4]);
    }
}

template <int EPI, bool CVTA, bool PERM>
__global__ __launch_bounds__(256, 2) void mm_tf32(
    const float* __restrict__ A, int lda,
    const float* __restrict__ W, int Nw,
    const float* __restrict__ bias,
    float* __restrict__ C, int ldc, int Nc,
    int K,
    size_t cSlice)
{
    extern __shared__ float smem_f[];
    const uint32_t sbase = smem_u32(smem_f);
    const int tid  = threadIdx.x;
    const int wid  = tid >> 5;
    const int lane = tid & 31;
    const int g    = lane >> 2;
    const int t4   = lane & 3;
    const int wm   = wid >> 2;
    const int wn   = wid & 3;
    const int mW   = wm * 64;
    const int nW   = wn * 32;
    const int m0 = blockIdx.y * 128;
    const int n0 = blockIdx.x * 128;
    const int kBase = blockIdx.z * K;
    const int iters = K / 32;

    C += (size_t)blockIdx.z * cSlice;
    const int ldw = K * gridDim.z;

    float acc[4][4][4];
    #pragma unroll
    for (int i = 0; i < 4; i++)
        #pragma unroll
        for (int j = 0; j < 4; j++)
            #pragma unroll
            for (int q = 0; q < 4; q++) acc[i][j][q] = 0.0f;

    // prologue: stage tiles 0 and 1 into buffers 0 and 1
    stage_tile(sbase, sbase + BUF_BYTES, A, lda, W, ldw, Nw, m0, n0, kBase, tid);
    cp_commit();
    stage_tile(sbase + 2 * BUF_BYTES, sbase + 3 * BUF_BYTES,
               A, lda, W, ldw, Nw, m0, n0, kBase + 32, tid);
    cp_commit();

    for (int it = 0; it < iters; it++) {
        cp_wait<1>();
        __syncthreads();

        if (it + 2 < iters) {
            int s = (it + 2) % 3;
            stage_tile(sbase + (uint32_t)(2 * s) * BUF_BYTES,
                       sbase + (uint32_t)(2 * s + 1) * BUF_BYTES,
                       A, lda, W, ldw, Nw, m0, n0, kBase + (it + 2) * 32, tid);
        }
        cp_commit();

        const int p = it % 3;
        const float* As = smem_f + (size_t)(2 * p) * TILE_FLOATS;
        const float* Bs = smem_f + (size_t)(2 * p + 1) * TILE_FLOATS;

        if (PERM) {
            // Register-lean: cache only B fragments across the i-loop; A
            // fragments are loaded per-i and consumed immediately.
            #pragma unroll
            for (int q = 0; q < 2; q++) {
                const int kf = t4 * 8 + q * 4;
                float4 bV[4];
                #pragma unroll
                for (int j = 0; j < 4; j++) {
                    int n = nW + j * 8 + g;
                    bV[j] = *(const float4*)&Bs[n * SM_STRIDE + kf];
                }
                #pragma unroll
                for (int i = 0; i < 4; i++) {
                    int r0 = mW + i * 16 + g;
                    float4 aLo = *(const float4*)&As[r0 * SM_STRIDE + kf];
                    float4 aHi = *(const float4*)&As[(r0 + 8) * SM_STRIDE + kf];
                    // sub 0: components (x,y); sub 1: components (z,w)
                    #pragma unroll
                    for (int j = 0; j < 4; j++)
                        mma_tf32(acc[i][j][0], acc[i][j][1],
                                 acc[i][j][2], acc[i][j][3],
                                 __float_as_uint(aLo.x), __float_as_uint(aHi.x),
                                 __float_as_uint(aLo.y), __float_as_uint(aHi.y),
                                 __float_as_uint(bV[j].x), __float_as_uint(bV[j].y));
                    #pragma unroll
                    for (int j = 0; j < 4; j++)
                        mma_tf32(acc[i][j][0], acc[i][j][1],
                                 acc[i][j][2], acc[i][j][3],
                                 __float_as_uint(aLo.z), __float_as_uint(aHi.z),
                                 __float_as_uint(aLo.w), __float_as_uint(aHi.w),
                                 __float_as_uint(bV[j].z), __float_as_uint(bV[j].w));
                }
            }
        } else {
            #pragma unroll
            for (int ks = 0; ks < 4; ks++) {
                const int k = ks * 8 + t4;
                uint32_t af[4][4];
                uint32_t bf[4][2];
                #pragma unroll
                for (int i = 0; i < 4; i++) {
                    int r0 = mW + i * 16 + g;
                    if (CVTA) {
                        af[i][0] = to_tf32(As[r0 * SM_STRIDE + k]);
                        af[i][1] = to_tf32(As[(r0 + 8) * SM_STRIDE + k]);
                        af[i][2] = to_tf32(As[r0 * SM_STRIDE + k + 4]);
                        af[i][3] = to_tf32(As[(r0 + 8) * SM_STRIDE + k + 4]);
                    } else {
                        af[i][0] = __float_as_uint(As[r0 * SM_STRIDE + k]);
                        af[i][1] = __float_as_uint(As[(r0 + 8) * SM_STRIDE + k]);
                        af[i][2] = __float_as_uint(As[r0 * SM_STRIDE + k + 4]);
                        af[i][3] = __float_as_uint(As[(r0 + 8) * SM_STRIDE + k + 4]);
                    }
                }
                #pragma unroll
                for (int j = 0; j < 4; j++) {
                    int n = nW + j * 8 + g;
                    bf[j][0] = __float_as_uint(Bs[n * SM_STRIDE + k]);
                    bf[j][1] = __float_as_uint(Bs[n * SM_STRIDE + k + 4]);
                }
                #pragma unroll
                for (int i = 0; i < 4; i++)
                    #pragma unroll
                    for (int j = 0; j < 4; j++)
                        mma_tf32(acc[i][j][0], acc[i][j][1], acc[i][j][2], acc[i][j][3],
                                 af[i][0], af[i][1], af[i][2], af[i][3],
                                 bf[j][0], bf[j][1]);
            }
        }
    }

    // ---- epilogue ----
    #pragma unroll
    for (int i = 0; i < 4; i++) {
        #pragma unroll
        for (int j = 0; j < 4; j++) {
            int col = n0 + nW + j * 8 + t4 * 2;
            if (col < Nc) {
                int row0 = m0 + mW + i * 16 + g;
                float2 v0 = make_float2(acc[i][j][0], acc[i][j][1]);
                float2 v1 = make_float2(acc[i][j][2], acc[i][j][3]);
                if (EPI == 1) {
                    v0.x = softplusf(v0.x + bias[col]);
                    v0.y = softplusf(v0.y + bias[col + 1]);
                    v1.x = softplusf(v1.x + bias[col]);
                    v1.y = softplusf(v1.y + bias[col + 1]);
                }
                *(float2*)&C[(size_t)row0 * ldc + col]       = v0;
                *(float2*)&C[(size_t)(row0 + 8) * ldc + col] = v1;
            }
        }
    }
}

// ---------------- split-K partial reduce ----------------
__global__ __launch_bounds__(256) void reduce_splits_kernel(
    const float* __restrict__ part, float* __restrict__ out, int n4)
{
    int i = blockIdx.x * blockDim.x + threadIdx.x;
    if (i >= n4) return;
    const float4* p = (const float4*)part;
    float4 s = p[i];
    #pragma unroll
    for (int k = 1; k < XP_SPLITS; k++) {
        float4 v = p[(size_t)k * n4 + i];
        s.x += v.x; s.y += v.y; s.z += v.z; s.w += v.w;
    }
    int cq = i % (NDBL / 4);
    if (cq < (DTRANK / 4)) {                 // cols 0..63 -> dt GEMM A operand
        int row = i / (NDBL / 4);
        int col = cq * 4;
        int blk = col & ~31;
        int pp = perm32(col & 31);
        float* orow = out + (size_t)row * NDBL + blk;
        orow[pp]      = round_tf32(s.x);
        orow[pp + 8]  = round_tf32(s.y);
        orow[pp + 16] = round_tf32(s.z);
        orow[pp + 24] = round_tf32(s.w);
    } else {
        ((float4*)out)[i] = s;
    }
}

// ------- 1) add + rmsnorm (output tf32-rounded, k-PERMUTED) ----------------
__global__ __launch_bounds__(256) void addnorm_kernel(
    const float* __restrict__ hs,
    const float* __restrict__ res,
    const float* __restrict__ w,
    float* __restrict__ out)
{
    int row = blockIdx.x;
    int tid = threadIdx.x;
    const float4* a4 = (const float4*)(hs  + (size_t)row * DMODEL);
    const float4* b4 = (const float4*)(res + (size_t)row * DMODEL);
    const float4* w4 = (const float4*)w;
    float4 v = a4[tid];
    float4 b = b4[tid];
    v.x += b.x; v.y += b.y; v.z += b.z; v.w += b.w;
    float ss = v.x*v.x + v.y*v.y + v.z*v.z + v.w*v.w;

    __shared__ float red[8];
    #pragma unroll
    for (int off = 16; off > 0; off >>= 1)
        ss += __shfl_xor_sync(0xffffffffu, ss, off);
    if ((tid & 31) == 0) red[tid >> 5] = ss;
    __syncthreads();
    if (tid < 32) {
        float s = (tid < 8) ? red[tid] : 0.0f;
        #pragma unroll
        for (int off = 4; off > 0; off >>= 1)
            s += __shfl_xor_sync(0xffffffffu, s, off);
        if (tid == 0) red[0] = s;
    }
    __syncthreads();
    float rstd = rsqrtf(red[0] * (1.0f / DMODEL) + 1e-5f);

    float4 ww = w4[tid];
    int col = tid * 4;
    int blk = col & ~31;
    int p = perm32(col & 31);
    float* orow = out + (size_t)row * DMODEL + blk;
    orow[p]      = round_tf32(v.x * rstd * ww.x);
    orow[p + 8]  = round_tf32(v.y * rstd * ww.y);
    orow[p + 16] = round_tf32(v.z * rstd * ww.z);
    orow[p + 24] = round_tf32(v.w * rstd * ww.w);
}

// ---------------- 3) causal depthwise conv (k=4) + bias + SiLU -------------
__global__ __launch_bounds__(256) void conv_silu_kernel(
    const float* __restrict__ xz,
    const float* __restrict__ cw,
    const float* __restrict__ cb,
    float* __restrict__ xc)
{
    int idx = blockIdx.x * blockDim.x + threadIdx.x;
    int dq = idx & (DINNER / 4 - 1);
    int t  = idx / (DINNER / 4);
    int d  = dq * 4;
    int l  = t & (LSEQ - 1);

    float4 bias4 = *(const float4*)&cb[d];
    float acc0 = bias4.x, acc1 = bias4.y, acc2 = bias4.z, acc3 = bias4.w;

    float4 w0 = *(const float4*)&cw[(d + 0) * 4];
    float4 w1 = *(const float4*)&cw[(d + 1) * 4];
    float4 w2 = *(const float4*)&cw[(d + 2) * 4];
    float4 w3 = *(const float4*)&cw[(d + 3) * 4];
    float wv0[4] = {w0.x, w0.y, w0.z, w0.w};
    float wv1[4] = {w1.x, w1.y, w1.z, w1.w};
    float wv2[4] = {w2.x, w2.y, w2.z, w2.w};
    float wv3[4] = {w3.x, w3.y, w3.z, w3.w};

    #pragma unroll
    for (int j = 0; j < 4; j++) {
        int lsrc = l - 3 + j;
        if (lsrc >= 0) {
            float4 v = *(const float4*)&xz[(size_t)(t - 3 + j) * (2 * DINNER) + d];
            acc0 = fmaf(v.x, wv0[j], acc0);
            acc1 = fmaf(v.y, wv1[j], acc1);
            acc2 = fmaf(v.z, wv2[j], acc2);
            acc3 = fmaf(v.w, wv3[j], acc3);
        }
    }
    float4 o;
    o.x = siluf(acc0); o.y = siluf(acc1); o.z = siluf(acc2); o.w = siluf(acc3);
    *(float4*)&xc[(size_t)t * DINNER + d] = o;
}

// ------- 4) selective scan (y tf32-rounded, k-PERMUTED) --------------------
__global__ __launch_bounds__(256) void scan_kernel(
    const float* __restrict__ dt,
    const float* __restrict__ xz,
    const float* __restrict__ xc,
    const float* __restrict__ xdbl,
    const float* __restrict__ A_log,
    const float* __restrict__ Dp,
    float* __restrict__ y)
{
    const int CH = 64;
    __shared__ float sdt[CH][16], sx[CH][16], sz[CH][16];
    __shared__ float sB[CH][16], sC[CH][16], sy[CH][16];

    int b  = blockIdx.x >> 7;
    int d0 = (blockIdx.x & 127) * 16;
    int tid = threadIdx.x;
    int c = tid >> 4;
    int n = tid & 15;
    int d = d0 + c;

    float Acoef = -expf(A_log[d * DSTATE + n]);
    float h = 0.0f;

    int e  = tid * 4;
    int le = e >> 4;
    int ie = e & 15;

    int ocol = d0 + ie;
    int oblk = ocol & ~31;
    int op   = perm32(ocol & 31);

    for (int l0 = 0; l0 < LSEQ; l0 += CH) {
        {
            size_t t = (size_t)b * LSEQ + l0 + le;
            *(float4*)&sdt[le][ie] = *(const float4*)&dt[t * DINNER + d0 + ie];
            *(float4*)&sx [le][ie] = *(const float4*)&xc[t * DINNER + d0 + ie];
            *(float4*)&sz [le][ie] = *(const float4*)&xz[t * (2 * DINNER) + DINNER + d0 + ie];
            *(float4*)&sB [le][ie] = *(const float4*)&xdbl[t * NDBL + DTRANK + ie];
            *(float4*)&sC [le][ie] = *(const float4*)&xdbl[t * NDBL + DTRANK + DSTATE + ie];
        }
        __syncthreads();

        #pragma unroll 4
        for (int ll = 0; ll < CH; ll++) {
            float dtv = sdt[ll][c];
            float xv  = sx[ll][c];
            float ea  = __expf(dtv * Acoef);
            h = fmaf(ea, h, dtv * xv * sB[ll][n]);
            float p = h * sC[ll][n];
            p += __shfl_xor_sync(0xffffffffu, p, 8);
            p += __shfl_xor_sync(0xffffffffu, p, 4);
            p += __shfl_xor_sync(0xffffffffu, p, 2);
            p += __shfl_xor_sync(0xffffffffu, p, 1);
            if (n == 0) sy[ll][c] = p;
        }
        __syncthreads();

        {
            size_t t = (size_t)b * LSEQ + l0 + le;
            float4 ys = *(float4*)&sy[le][ie];
            float4 xs = *(float4*)&sx[le][ie];
            float4 zs = *(float4*)&sz[le][ie];
            float4 dd = *(const float4*)&Dp[d0 + ie];
            float* orow = y + t * DINNER + oblk;
            orow[op]      = round_tf32((ys.x + xs.x * dd.x) * siluf(zs.x));
            orow[op + 8]  = round_tf32((ys.y + xs.y * dd.y) * siluf(zs.y));
            orow[op + 16] = round_tf32((ys.z + xs.z * dd.z) * siluf(zs.z));
            orow[op + 24] = round_tf32((ys.w + xs.w * dd.w) * siluf(zs.w));
        }
        __syncthreads();
    }
}

// ---------------- launcher ----------------
extern "C" void kernel_launch(void* const* d_in, const int* in_sizes, int n_in,
                              void* d_out, int out_size)
{
    (void)in_sizes; (void)n_in; (void)out_size;
    const float* hs        = (const float*)d_in[1];
    const float* residual  = (const float*)d_in[2];
    const float* norm_w    = (const float*)d_in[3];
    const float* in_proj_w = (const float*)d_in[4];
    const float* conv_w    = (const float*)d_in[5];
    const float* conv_b    = (const float*)d_in[6];
    const float* x_proj_w  = (const float*)d_in[7];
    const float* dt_proj_w = (const float*)d_in[8];
    const float* dt_proj_b = (const float*)d_in[9];
    const float* A_log     = (const float*)d_in[10];
    const float* D_param   = (const float*)d_in[11];
    const float* out_proj_w= (const float*)d_in[12];
    float* out = (float*)d_out;

    static float* scratch = nullptr;
    if (!scratch) {
        void* p = nullptr;
        cudaGetSymbolAddress(&p, g_scratch);
        scratch = (float*)p;
        cudaFuncSetAttribute(mm_tf32<0, false, true>,  cudaFuncAttributeMaxDynamicSharedMemorySize, MM_SMEM_BYTES);
        cudaFuncSetAttribute(mm_tf32<0, true,  false>, cudaFuncAttributeMaxDynamicSharedMemorySize, MM_SMEM_BYTES);
        cudaFuncSetAttribute(mm_tf32<1, false, true>,  cudaFuncAttributeMaxDynamicSharedMemorySize, MM_SMEM_BYTES);
    }
    float* g_h    = scratch + OFF_H;
    float* g_xz   = scratch + OFF_XZ;
    float* g_xc   = scratch + OFF_XC;
    float* g_xdbl = scratch + OFF_XDBL;
    float* g_dt   = scratch + OFF_DT;
    float* g_y    = scratch + OFF_Y;
    float* g_xp   = scratch + OFF_XP;
    float* g_win  = scratch + OFF_WIN;
    float* g_wxp  = scratch + OFF_WXP;
    float* g_wdt  = scratch + OFF_WDT;
    float* g_wop  = scratch + OFF_WOP;

    // 0) pre-round weights to tf32; permute k for the PERM GEMMs
    round_perm_kernel<<<(int)(W_IN_SZ / 4 + 255) / 256, 256>>>(
        (const float4*)in_proj_w, g_win, (int)(W_IN_SZ / 4), DMODEL);
    round_copy_kernel<<<(int)(W_XP_SZ / 4 + 255) / 256, 256>>>(
        (const float4*)x_proj_w, (float4*)g_wxp, (int)(W_XP_SZ / 4));
    round_perm_kernel<<<(int)(W_DT_SZ / 4 + 255) / 256, 256>>>(
        (const float4*)dt_proj_w, g_wdt, (int)(W_DT_SZ / 4), DTRANK);
    round_perm_kernel<<<(int)(W_OP_SZ / 4 + 255) / 256, 256>>>(
        (const float4*)out_proj_w, g_wop, (int)(W_OP_SZ / 4), DINNER);

    // 1) h = round_tf32(rmsnorm(hidden + residual) * w), k-permuted
    addnorm_kernel<<<NTOK, 256>>>(hs, residual, norm_w, g_h);

    // 2) xz = h @ in_proj_w^T   [4096 x 4096], K=1024  (PERM)
    mm_tf32<0, false, true><<<dim3(4096 / 128, NTOK / 128, 1), 256, MM_SMEM_BYTES>>>(
        g_h, DMODEL, g_win, 2 * DINNER, nullptr,
        g_xz, 2 * DINNER, 2 * DINNER, DMODEL, 0);

    // 3) xc = silu(causal_conv(x) + b)
    conv_silu_kernel<<<(NTOK * DINNER / 4) / 256, 256>>>(g_xz, conv_w, conv_b, g_xc);

    // 4) x_dbl partials = xc @ x_proj_w^T   [4096 x 96], K=2048, split-K=8 (non-PERM)
    mm_tf32<0, true, false><<<dim3(1, NTOK / 128, XP_SPLITS), 256, MM_SMEM_BYTES>>>(
        g_xc, DINNER, g_wxp, NDBL, nullptr,
        g_xp, NDBL, NDBL, DINNER / XP_SPLITS, (size_t)NTOK * NDBL);
    reduce_splits_kernel<<<(NTOK * NDBL / 4 + 255) / 256, 256>>>(
        g_xp, g_xdbl, NTOK * NDBL / 4);

    // 5) dt = softplus(x_dbl[:, :64] @ dt_proj_w^T + b)   [4096 x 2048], K=64 (PERM)
    mm_tf32<1, false, true><<<dim3(DINNER / 128, NTOK / 128, 1), 256, MM_SMEM_BYTES>>>(
        g_xdbl, NDBL, g_wdt, DINNER, dt_proj_b,
        g_dt, DINNER, DINNER, DTRANK, 0);

    // 6) selective scan + gate -> y (tf32-rounded, k-permuted for out_proj)
    scan_kernel<<<BATCH * (DINNER / 16), 256>>>(
        g_dt, g_xz, g_xc, g_xdbl, A_log, D_param, g_y);

    // 7) out = y @ out_proj_w^T   [4096 x 1024], K=2048  (PERM)
    mm_tf32<0, false, true><<<dim3(DMODEL / 128, NTOK / 128, 1), 256, MM_SMEM_BYTES>>>(
        g_y, DINNER, g_wop, DMODEL, nullptr,
        out, DMODEL, DMODEL, DINNER, 0);
}

// round 9
// speedup vs baseline: 2.0298x; 2.0298x over previous
#include <cuda_runtime.h>
#include <cuda_fp16.h>
#include <cstdint>

// ---------------- Problem constants ----------------
#define BATCH   2
#define LSEQ    2048
#define NTOK    (BATCH * LSEQ)      // 4096 tokens
#define DMODEL  1024
#define DINNER  2048
#define DSTATE  16
#define DCONV   4
#define DTRANK  64
#define NDBL    (DTRANK + 2 * DSTATE)   // 96
#define XP_SPLITS 8

// ---------------- Scratch (device globals; no allocation allowed) ----------
// fp32 regions (sizes in floats)
#define OFF_XZ    ((size_t)0)                                   // NTOK*4096
#define OFF_XC    (OFF_XZ   + (size_t)NTOK * 2 * DINNER)        // NTOK*2048
#define OFF_XDBL  (OFF_XC   + (size_t)NTOK * DINNER)            // NTOK*96
#define OFF_DT    (OFF_XDBL + (size_t)NTOK * NDBL)              // NTOK*2048
#define OFF_XP    (OFF_DT   + (size_t)NTOK * DINNER)            // 8*NTOK*96
// half regions (sizes in floats = halfs/2)
#define OFF_H2    (OFF_XP   + (size_t)XP_SPLITS * NTOK * NDBL)  // NTOK*1024/2
#define OFF_XCH   (OFF_H2   + (size_t)NTOK * DMODEL / 2)        // NTOK*2048/2
#define OFF_DTL   (OFF_XCH  + (size_t)NTOK * DINNER / 2)        // NTOK*64/2
#define OFF_Y2    (OFF_DTL  + (size_t)NTOK * DTRANK / 2)        // NTOK*2048/2
#define OFF_WIN2  (OFF_Y2   + (size_t)NTOK * DINNER / 2)
#define OFF_WXP2  (OFF_WIN2 + (size_t)2 * DINNER * DMODEL / 2)
#define OFF_WDT2  (OFF_WXP2 + (size_t)NDBL * DINNER / 2)
#define OFF_WOP2  (OFF_WDT2 + (size_t)DINNER * DTRANK / 2)
#define SCRATCH_FLOATS (OFF_WOP2 + (size_t)DMODEL * DINNER / 2)

__device__ float g_scratch[SCRATCH_FLOATS];

// ---------------- helpers ----------------
__device__ __forceinline__ float siluf(float z) {
    return z * (1.0f / (1.0f + __expf(-z)));
}
__device__ __forceinline__ float softplusf(float v) {
    return fmaxf(v, 0.0f) + log1pf(expf(-fabsf(v)));
}

__device__ __forceinline__ uint32_t smem_u32(const void* p) {
    uint32_t addr;
    asm("{ .reg .u64 tmp; cvta.to.shared.u64 tmp, %1; cvt.u32.u64 %0, tmp; }"
        : "=r"(addr) : "l"(p));
    return addr;
}

__device__ __forceinline__ void cp16(uint32_t dst, const void* src) {
    asm volatile("cp.async.cg.shared.global [%0], [%1], 16;" :: "r"(dst), "l"(src));
}
__device__ __forceinline__ void cp_commit() {
    asm volatile("cp.async.commit_group;");
}
template <int N>
__device__ __forceinline__ void cp_wait() {
    asm volatile("cp.async.wait_group %0;" :: "n"(N));
}

__device__ __forceinline__ void ldsm_x4(
    uint32_t& r0, uint32_t& r1, uint32_t& r2, uint32_t& r3, uint32_t addr)
{
    asm volatile(
        "ldmatrix.sync.aligned.m8n8.x4.shared.b16 {%0,%1,%2,%3}, [%4];"
        : "=r"(r0), "=r"(r1), "=r"(r2), "=r"(r3) : "r"(addr));
}

// D(16x8) += A(16x16) * B(16x8), f16 inputs, f32 accumulate
__device__ __forceinline__ void mma_f16(
    float& c0, float& c1, float& c2, float& c3,
    uint32_t a0, uint32_t a1, uint32_t a2, uint32_t a3,
    uint32_t b0, uint32_t b1)
{
    asm volatile(
        "mma.sync.aligned.m16n8k16.row.col.f32.f16.f16.f32 "
        "{%0,%1,%2,%3}, {%4,%5,%6,%7}, {%8,%9}, {%0,%1,%2,%3};"
        : "+f"(c0), "+f"(c1), "+f"(c2), "+f"(c3)
        : "r"(a0), "r"(a1), "r"(a2), "r"(a3), "r"(b0), "r"(b1));
}

__device__ __forceinline__ uint32_t pack_h2(float a, float b) {
    __half2 h = __floats2half2_rn(a, b);
    return *(uint32_t*)&h;
}

// ------------- weight fp32 -> fp16 copy ------------------------------------
__global__ __launch_bounds__(256) void w2h_kernel(
    const float4* __restrict__ in, uint2* __restrict__ out, int n4)
{
    int i = blockIdx.x * blockDim.x + threadIdx.x;
    if (i >= n4) return;
    float4 v = in[i];
    out[i] = make_uint2(pack_h2(v.x, v.y), pack_h2(v.z, v.w));
}

// ---------------- FP16 tensor-core GEMM: C[m,n] = sum_k A[m,k] * W[n,k] ----
// CTA: 128x128x32, 256 threads, 8 warps (2 M x 4 N), warp 64x32.
// 3-stage cp.async pipeline, one __syncthreads per k-iter, ldmatrix fragments.
// EPI: 0 = plain fp32 store, 1 = softplus(c + bias[n]).
// Split-K via gridDim.z.
#define ROWB 80                             // bytes per smem row (64 data + 16 pad)
#define TILE_B (128 * ROWB)                 // 10240
#define STAGE_B (2 * TILE_B)                // A + B
#define MM_SMEM_BYTES (3 * STAGE_B)         // 61440

__device__ __forceinline__ void stage_tile(
    uint32_t sA, uint32_t sB,
    const __half* __restrict__ A, int lda,
    const __half* __restrict__ W, int ldw, int Nw,
    int m0, int n0, int k0, int tid)
{
    #pragma unroll
    for (int i = 0; i < 2; i++) {
        int idx = i * 256 + tid;            // 0..511
        int row = idx >> 2;
        int c   = idx & 3;                  // 16B chunk (8 halfs)
        cp16(sA + (uint32_t)(row * ROWB + c * 16),
             &A[(size_t)(m0 + row) * lda + k0 + c * 8]);
    }
    #pragma unroll
    for (int i = 0; i < 2; i++) {
        int idx = i * 256 + tid;
        int row = idx >> 2;
        int c   = idx & 3;
        int n = n0 + row;
        int nn = (n < Nw) ? n : 0;          // clamp; garbage cols never stored
        cp16(sB + (uint32_t)(row * ROWB + c * 16),
             &W[(size_t)nn * ldw + k0 + c * 8]);
    }
}

template <int EPI>
__global__ __launch_bounds__(256, 2) void mm_f16(
    const __half* __restrict__ A, int lda,
    const __half* __restrict__ W, int Nw,     // valid W rows
    const float* __restrict__ bias,
    float* __restrict__ C, int ldc, int Nc,   // valid C cols
    int K,                                     // K per z-slice
    size_t cSlice)                             // C offset per z-slice
{
    extern __shared__ char smem_c[];
    const uint32_t sbase = smem_u32(smem_c);
    const int tid  = threadIdx.x;
    const int wid  = tid >> 5;
    const int lane = tid & 31;
    const int g    = lane >> 2;
    const int t4   = lane & 3;
    const int wm   = wid >> 2;                // 0..1
    const int wn   = wid & 3;                 // 0..3
    const int mW   = wm * 64;
    const int nW   = wn * 32;
    const int m0 = blockIdx.y * 128;
    const int n0 = blockIdx.x * 128;
    const int kBase = blockIdx.z * K;
    const int iters = K / 32;

    C += (size_t)blockIdx.z * cSlice;
    const int ldw = K * gridDim.z;

    // per-lane ldmatrix offsets (same shape for A and B):
    // lanes 0-15 -> rows 0-15 of the 16-row block, lanes 16-31 -> same rows,
    // next 16B chunk (k+8).
    const uint32_t offA = (uint32_t)((mW + (lane & 15)) * ROWB + (lane >> 4) * 16);
    const uint32_t offB = (uint32_t)((nW + (lane & 15)) * ROWB + (lane >> 4) * 16);

    float acc[4][4][4];
    #pragma unroll
    for (int i = 0; i < 4; i++)
        #pragma unroll
        for (int j = 0; j < 4; j++)
            #pragma unroll
            for (int q = 0; q < 4; q++) acc[i][j][q] = 0.0f;

    // prologue: stage tiles 0 and 1
    stage_tile(sbase, sbase + TILE_B, A, lda, W, ldw, Nw, m0, n0, kBase, tid);
    cp_commit();
    stage_tile(sbase + STAGE_B, sbase + STAGE_B + TILE_B,
               A, lda, W, ldw, Nw, m0, n0, kBase + 32, tid);
    cp_commit();

    for (int it = 0; it < iters; it++) {
        cp_wait<1>();
        __syncthreads();

        if (it + 2 < iters) {
            int s = (it + 2) % 3;
            stage_tile(sbase + (uint32_t)s * STAGE_B,
                       sbase + (uint32_t)s * STAGE_B + TILE_B,
                       A, lda, W, ldw, Nw, m0, n0, kBase + (it + 2) * 32, tid);
        }
        cp_commit();

        const uint32_t aBase = sbase + (uint32_t)(it % 3) * STAGE_B;
        const uint32_t bBase = aBase + TILE_B;

        #pragma unroll
        for (int ks = 0; ks < 2; ks++) {       // two k16 steps per 32-k tile
            // B fragments: jpair 0 (n 0-15), jpair 1 (n 16-31)
            uint32_t b0r[4], b1r[4];
            ldsm_x4(b0r[0], b0r[1], b0r[2], b0r[3], bBase + offB + ks * 32);
            ldsm_x4(b1r[0], b1r[1], b1r[2], b1r[3],
                    bBase + offB + 16 * ROWB + ks * 32);
            #pragma unroll
            for (int i = 0; i < 4; i++) {
                uint32_t a0, a1, a2, a3;
                ldsm_x4(a0, a1, a2, a3,
                        aBase + offA + (uint32_t)(i * 16 * ROWB) + ks * 32);
                mma_f16(acc[i][0][0], acc[i][0][1], acc[i][0][2], acc[i][0][3],
                        a0, a1, a2, a3, b0r[0], b0r[2]);
                mma_f16(acc[i][1][0], acc[i][1][1], acc[i][1][2], acc[i][1][3],
                        a0, a1, a2, a3, b0r[1], b0r[3]);
                mma_f16(acc[i][2][0], acc[i][2][1], acc[i][2][2], acc[i][2][3],
                        a0, a1, a2, a3, b1r[0], b1r[2]);
                mma_f16(acc[i][3][0], acc[i][3][1], acc[i][3][2], acc[i][3][3],
                        a0, a1, a2, a3, b1r[1], b1r[3]);
            }
        }
    }

    // ---- epilogue: registers -> global (float2 stores, 32B coalesced) ----
    #pragma unroll
    for (int i = 0; i < 4; i++) {
        #pragma unroll
        for (int j = 0; j < 4; j++) {
            int col = n0 + nW + j * 8 + t4 * 2;
            if (col < Nc) {
                int row0 = m0 + mW + i * 16 + g;
                float2 v0 = make_float2(acc[i][j][0], acc[i][j][1]);
                float2 v1 = make_float2(acc[i][j][2], acc[i][j][3]);
                if (EPI == 1) {
                    v0.x = softplusf(v0.x + bias[col]);
                    v0.y = softplusf(v0.y + bias[col + 1]);
                    v1.x = softplusf(v1.x + bias[col]);
                    v1.y = softplusf(v1.y + bias[col + 1]);
                }
                *(float2*)&C[(size_t)row0 * ldc + col]       = v0;
                *(float2*)&C[(size_t)(row0 + 8) * ldc + col] = v1;
            }
        }
    }
}

// ---------------- split-K partial reduce ------------------------------------
// Cols < DTRANK -> half (A of dt GEMM) into dtlow; cols >= DTRANK -> fp32 xdbl.
__global__ __launch_bounds__(256) void reduce_splits_kernel(
    const float* __restrict__ part, float* __restrict__ out,
    __half* __restrict__ dtlow, int n4)
{
    int i = blockIdx.x * blockDim.x + threadIdx.x;
    if (i >= n4) return;
    const float4* p = (const float4*)part;
    float4 s = p[i];
    #pragma unroll
    for (int k = 1; k < XP_SPLITS; k++) {
        float4 v = p[(size_t)k * n4 + i];
        s.x += v.x; s.y += v.y; s.z += v.z; s.w += v.w;
    }
    int cq = i % (NDBL / 4);
    if (cq < (DTRANK / 4)) {
        int row = i / (NDBL / 4);
        *(uint2*)&dtlow[(size_t)row * DTRANK + cq * 4] =
            make_uint2(pack_h2(s.x, s.y), pack_h2(s.z, s.w));
    } else {
        ((float4*)out)[i] = s;
    }
}

// ------- 1) add + rmsnorm -> fp16 (natural order) --------------------------
__global__ __launch_bounds__(256) void addnorm_kernel(
    const float* __restrict__ hs,
    const float* __restrict__ res,
    const float* __restrict__ w,
    __half* __restrict__ out)
{
    int row = blockIdx.x;
    int tid = threadIdx.x;
    const float4* a4 = (const float4*)(hs  + (size_t)row * DMODEL);
    const float4* b4 = (const float4*)(res + (size_t)row * DMODEL);
    const float4* w4 = (const float4*)w;
    float4 v = a4[tid];
    float4 b = b4[tid];
    v.x += b.x; v.y += b.y; v.z += b.z; v.w += b.w;
    float ss = v.x*v.x + v.y*v.y + v.z*v.z + v.w*v.w;

    __shared__ float red[8];
    #pragma unroll
    for (int off = 16; off > 0; off >>= 1)
        ss += __shfl_xor_sync(0xffffffffu, ss, off);
    if ((tid & 31) == 0) red[tid >> 5] = ss;
    __syncthreads();
    if (tid < 32) {
        float s = (tid < 8) ? red[tid] : 0.0f;
        #pragma unroll
        for (int off = 4; off > 0; off >>= 1)
            s += __shfl_xor_sync(0xffffffffu, s, off);
        if (tid == 0) red[0] = s;
    }
    __syncthreads();
    float rstd = rsqrtf(red[0] * (1.0f / DMODEL) + 1e-5f);

    float4 ww = w4[tid];
    *(uint2*)&out[(size_t)row * DMODEL + tid * 4] =
        make_uint2(pack_h2(v.x * rstd * ww.x, v.y * rstd * ww.y),
                   pack_h2(v.z * rstd * ww.z, v.w * rstd * ww.w));
}

// ------- 3) causal depthwise conv + bias + SiLU -> fp32 (scan) + fp16 ------
__global__ __launch_bounds__(256) void conv_silu_kernel(
    const float* __restrict__ xz,
    const float* __restrict__ cw,
    const float* __restrict__ cb,
    float* __restrict__ xc,
    __half* __restrict__ xch)
{
    int idx = blockIdx.x * blockDim.x + threadIdx.x;
    int dq = idx & (DINNER / 4 - 1);
    int t  = idx / (DINNER / 4);
    int d  = dq * 4;
    int l  = t & (LSEQ - 1);

    float4 bias4 = *(const float4*)&cb[d];
    float acc0 = bias4.x, acc1 = bias4.y, acc2 = bias4.z, acc3 = bias4.w;

    float4 w0 = *(const float4*)&cw[(d + 0) * 4];
    float4 w1 = *(const float4*)&cw[(d + 1) * 4];
    float4 w2 = *(const float4*)&cw[(d + 2) * 4];
    float4 w3 = *(const float4*)&cw[(d + 3) * 4];
    float wv0[4] = {w0.x, w0.y, w0.z, w0.w};
    float wv1[4] = {w1.x, w1.y, w1.z, w1.w};
    float wv2[4] = {w2.x, w2.y, w2.z, w2.w};
    float wv3[4] = {w3.x, w3.y, w3.z, w3.w};

    #pragma unroll
    for (int j = 0; j < 4; j++) {
        int lsrc = l - 3 + j;
        if (lsrc >= 0) {
            float4 v = *(const float4*)&xz[(size_t)(t - 3 + j) * (2 * DINNER) + d];
            acc0 = fmaf(v.x, wv0[j], acc0);
            acc1 = fmaf(v.y, wv1[j], acc1);
            acc2 = fmaf(v.z, wv2[j], acc2);
            acc3 = fmaf(v.w, wv3[j], acc3);
        }
    }
    float4 o;
    o.x = siluf(acc0); o.y = siluf(acc1); o.z = siluf(acc2); o.w = siluf(acc3);
    *(float4*)&xc[(size_t)t * DINNER + d] = o;
    *(uint2*)&xch[(size_t)t * DINNER + d] =
        make_uint2(pack_h2(o.x, o.y), pack_h2(o.z, o.w));
}

// ------- 4) selective scan -> y fp16 (natural order) -----------------------
__global__ __launch_bounds__(256) void scan_kernel(
    const float* __restrict__ dt,
    const float* __restrict__ xz,
    const float* __restrict__ xc,
    const float* __restrict__ xdbl,
    const float* __restrict__ A_log,
    const float* __restrict__ Dp,
    __half* __restrict__ y)
{
    const int CH = 64;
    __shared__ float sdt[CH][16], sx[CH][16], sz[CH][16];
    __shared__ float sB[CH][16], sC[CH][16], sy[CH][16];

    int b  = blockIdx.x >> 7;
    int d0 = (blockIdx.x & 127) * 16;
    int tid = threadIdx.x;
    int c = tid >> 4;
    int n = tid & 15;
    int d = d0 + c;

    float Acoef = -expf(A_log[d * DSTATE + n]);
    float h = 0.0f;

    int e  = tid * 4;
    int le = e >> 4;
    int ie = e & 15;

    for (int l0 = 0; l0 < LSEQ; l0 += CH) {
        {
            size_t t = (size_t)b * LSEQ + l0 + le;
            *(float4*)&sdt[le][ie] = *(const float4*)&dt[t * DINNER + d0 + ie];
            *(float4*)&sx [le][ie] = *(const float4*)&xc[t * DINNER + d0 + ie];
            *(float4*)&sz [le][ie] = *(const float4*)&xz[t * (2 * DINNER) + DINNER + d0 + ie];
            *(float4*)&sB [le][ie] = *(const float4*)&xdbl[t * NDBL + DTRANK + ie];
            *(float4*)&sC [le][ie] = *(const float4*)&xdbl[t * NDBL + DTRANK + DSTATE + ie];
        }
        __syncthreads();

        #pragma unroll 4
        for (int ll = 0; ll < CH; ll++) {
            float dtv = sdt[ll][c];
            float xv  = sx[ll][c];
            float ea  = __expf(dtv * Acoef);
            h = fmaf(ea, h, dtv * xv * sB[ll][n]);
            float p = h * sC[ll][n];
            p += __shfl_xor_sync(0xffffffffu, p, 8);
            p += __shfl_xor_sync(0xffffffffu, p, 4);
            p += __shfl_xor_sync(0xffffffffu, p, 2);
            p += __shfl_xor_sync(0xffffffffu, p, 1);
            if (n == 0) sy[ll][c] = p;
        }
        __syncthreads();

        {
            size_t t = (size_t)b * LSEQ + l0 + le;
            float4 ys = *(float4*)&sy[le][ie];
            float4 xs = *(float4*)&sx[le][ie];
            float4 zs = *(float4*)&sz[le][ie];
            float4 dd = *(const float4*)&Dp[d0 + ie];
            float o0 = (ys.x + xs.x * dd.x) * siluf(zs.x);
            float o1 = (ys.y + xs.y * dd.y) * siluf(zs.y);
            float o2 = (ys.z + xs.z * dd.z) * siluf(zs.z);
            float o3 = (ys.w + xs.w * dd.w) * siluf(zs.w);
            *(uint2*)&y[t * DINNER + d0 + ie] =
                make_uint2(pack_h2(o0, o1), pack_h2(o2, o3));
        }
        __syncthreads();
    }
}

// ---------------- launcher ----------------
extern "C" void kernel_launch(void* const* d_in, const int* in_sizes, int n_in,
                              void* d_out, int out_size)
{
    (void)in_sizes; (void)n_in; (void)out_size;
    const float* hs        = (const float*)d_in[1];
    const float* residual  = (const float*)d_in[2];
    const float* norm_w    = (const float*)d_in[3];
    const float* in_proj_w = (const float*)d_in[4];
    const float* conv_w    = (const float*)d_in[5];
    const float* conv_b    = (const float*)d_in[6];
    const float* x_proj_w  = (const float*)d_in[7];
    const float* dt_proj_w = (const float*)d_in[8];
    const float* dt_proj_b = (const float*)d_in[9];
    const float* A_log     = (const float*)d_in[10];
    const float* D_param   = (const float*)d_in[11];
    const float* out_proj_w= (const float*)d_in[12];
    float* out = (float*)d_out;

    static float* scratch = nullptr;
    if (!scratch) {
        void* p = nullptr;
        cudaGetSymbolAddress(&p, g_scratch);
        scratch = (float*)p;
        cudaFuncSetAttribute(mm_f16<0>, cudaFuncAttributeMaxDynamicSharedMemorySize, MM_SMEM_BYTES);
        cudaFuncSetAttribute(mm_f16<1>, cudaFuncAttributeMaxDynamicSharedMemorySize, MM_SMEM_BYTES);
    }
    float*  g_xz   = scratch + OFF_XZ;
    float*  g_xc   = scratch + OFF_XC;
    float*  g_xdbl = scratch + OFF_XDBL;
    float*  g_dt   = scratch + OFF_DT;
    float*  g_xp   = scratch + OFF_XP;
    __half* g_h2   = (__half*)(scratch + OFF_H2);
    __half* g_xch  = (__half*)(scratch + OFF_XCH);
    __half* g_dtl  = (__half*)(scratch + OFF_DTL);
    __half* g_y2   = (__half*)(scratch + OFF_Y2);
    __half* g_win  = (__half*)(scratch + OFF_WIN2);
    __half* g_wxp  = (__half*)(scratch + OFF_WXP2);
    __half* g_wdt  = (__half*)(scratch + OFF_WDT2);
    __half* g_wop  = (__half*)(scratch + OFF_WOP2);

    // 0) weights fp32 -> fp16
    w2h_kernel<<<(int)(2 * DINNER * DMODEL / 4 + 255) / 256, 256>>>(
        (const float4*)in_proj_w, (uint2*)g_win, 2 * DINNER * DMODEL / 4);
    w2h_kernel<<<(int)(NDBL * DINNER / 4 + 255) / 256, 256>>>(
        (const float4*)x_proj_w, (uint2*)g_wxp, NDBL * DINNER / 4);
    w2h_kernel<<<(int)(DINNER * DTRANK / 4 + 255) / 256, 256>>>(
        (const float4*)dt_proj_w, (uint2*)g_wdt, DINNER * DTRANK / 4);
    w2h_kernel<<<(int)(DMODEL * DINNER / 4 + 255) / 256, 256>>>(
        (const float4*)out_proj_w, (uint2*)g_wop, DMODEL * DINNER / 4);

    // 1) h = fp16(rmsnorm(hidden + residual) * w)
    addnorm_kernel<<<NTOK, 256>>>(hs, residual, norm_w, g_h2);

    // 2) xz = h @ in_proj_w^T   [4096 x 4096], K=1024
    mm_f16<0><<<dim3(4096 / 128, NTOK / 128, 1), 256, MM_SMEM_BYTES>>>(
        g_h2, DMODEL, g_win, 2 * DINNER, nullptr,
        g_xz, 2 * DINNER, 2 * DINNER, DMODEL, 0);

    // 3) xc = silu(causal_conv(x) + b)  -> fp32 (scan) + fp16 (x_proj)
    conv_silu_kernel<<<(NTOK * DINNER / 4) / 256, 256>>>(
        g_xz, conv_w, conv_b, g_xc, g_xch);

    // 4) x_dbl partials = xc @ x_proj_w^T   [4096 x 96], K=2048, split-K=8
    mm_f16<0><<<dim3(1, NTOK / 128, XP_SPLITS), 256, MM_SMEM_BYTES>>>(
        g_xch, DINNER, g_wxp, NDBL, nullptr,
        g_xp, NDBL, NDBL, DINNER / XP_SPLITS, (size_t)NTOK * NDBL);
    reduce_splits_kernel<<<(NTOK * NDBL / 4 + 255) / 256, 256>>>(
        g_xp, g_xdbl, g_dtl, NTOK * NDBL / 4);

    // 5) dt = softplus(dtlow @ dt_proj_w^T + b)   [4096 x 2048], K=64
    mm_f16<1><<<dim3(DINNER / 128, NTOK / 128, 1), 256, MM_SMEM_BYTES>>>(
        g_dtl, DTRANK, g_wdt, DINNER, dt_proj_b,
        g_dt, DINNER, DINNER, DTRANK, 0);

    // 6) selective scan + gate -> y (fp16 for out_proj)
    scan_kernel<<<BATCH * (DINNER / 16), 256>>>(
        g_dt, g_xz, g_xc, g_xdbl, A_log, D_param, g_y2);

    // 7) out = y @ out_proj_w^T   [4096 x 1024], K=2048
    mm_f16<0><<<dim3(DMODEL / 128, NTOK / 128, 1), 256, MM_SMEM_BYTES>>>(
        g_y2, DINNER, g_wop, DMODEL, nullptr,
        out, DMODEL, DMODEL, DINNER, 0);
}

// round 10
// speedup vs baseline: 2.1563x; 1.0624x over previous
#include <cuda_runtime.h>
#include <cuda_fp16.h>
#include <cstdint>

// ---------------- Problem constants ----------------
#define BATCH   2
#define LSEQ    2048
#define NTOK    (BATCH * LSEQ)      // 4096 tokens
#define DMODEL  1024
#define DINNER  2048
#define DSTATE  16
#define DCONV   4
#define DTRANK  64
#define NDBL    (DTRANK + 2 * DSTATE)   // 96
#define XP_SPLITS 8

// ---------------- Scratch (device globals; no allocation allowed) ----------
// fp32 regions (sizes in floats)
#define OFF_XZ    ((size_t)0)                                   // NTOK*4096
#define OFF_XC    (OFF_XZ   + (size_t)NTOK * 2 * DINNER)        // NTOK*2048
#define OFF_XDBL  (OFF_XC   + (size_t)NTOK * DINNER)            // NTOK*96
#define OFF_DT    (OFF_XDBL + (size_t)NTOK * NDBL)              // NTOK*2048
#define OFF_XP    (OFF_DT   + (size_t)NTOK * DINNER)            // 8*NTOK*96
// half regions (sizes in floats = halfs/2)
#define OFF_H2    (OFF_XP   + (size_t)XP_SPLITS * NTOK * NDBL)
#define OFF_XCH   (OFF_H2   + (size_t)NTOK * DMODEL / 2)
#define OFF_DTL   (OFF_XCH  + (size_t)NTOK * DINNER / 2)
#define OFF_Y2    (OFF_DTL  + (size_t)NTOK * DTRANK / 2)
#define OFF_WIN2  (OFF_Y2   + (size_t)NTOK * DINNER / 2)
#define OFF_WXP2  (OFF_WIN2 + (size_t)2 * DINNER * DMODEL / 2)
#define OFF_WDT2  (OFF_WXP2 + (size_t)NDBL * DINNER / 2)
#define OFF_WOP2  (OFF_WDT2 + (size_t)DINNER * DTRANK / 2)
#define SCRATCH_FLOATS (OFF_WOP2 + (size_t)DMODEL * DINNER / 2)

__device__ float g_scratch[SCRATCH_FLOATS];

// ---------------- helpers ----------------
__device__ __forceinline__ float siluf(float z) {
    return z * (1.0f / (1.0f + __expf(-z)));
}
__device__ __forceinline__ float softplusf(float v) {
    return fmaxf(v, 0.0f) + log1pf(expf(-fabsf(v)));
}

__device__ __forceinline__ uint32_t smem_u32(const void* p) {
    uint32_t addr;
    asm("{ .reg .u64 tmp; cvta.to.shared.u64 tmp, %1; cvt.u32.u64 %0, tmp; }"
        : "=r"(addr) : "l"(p));
    return addr;
}

__device__ __forceinline__ void cp16(uint32_t dst, const void* src) {
    asm volatile("cp.async.cg.shared.global [%0], [%1], 16;" :: "r"(dst), "l"(src));
}
__device__ __forceinline__ void cp_commit() {
    asm volatile("cp.async.commit_group;");
}
template <int N>
__device__ __forceinline__ void cp_wait() {
    asm volatile("cp.async.wait_group %0;" :: "n"(N));
}

__device__ __forceinline__ void ldsm_x4(
    uint32_t& r0, uint32_t& r1, uint32_t& r2, uint32_t& r3, uint32_t addr)
{
    asm volatile(
        "ldmatrix.sync.aligned.m8n8.x4.shared.b16 {%0,%1,%2,%3}, [%4];"
        : "=r"(r0), "=r"(r1), "=r"(r2), "=r"(r3) : "r"(addr));
}

// D(16x8) += A(16x16) * B(16x8), f16 inputs, f32 accumulate
__device__ __forceinline__ void mma_f16(
    float& c0, float& c1, float& c2, float& c3,
    uint32_t a0, uint32_t a1, uint32_t a2, uint32_t a3,
    uint32_t b0, uint32_t b1)
{
    asm volatile(
        "mma.sync.aligned.m16n8k16.row.col.f32.f16.f16.f32 "
        "{%0,%1,%2,%3}, {%4,%5,%6,%7}, {%8,%9}, {%0,%1,%2,%3};"
        : "+f"(c0), "+f"(c1), "+f"(c2), "+f"(c3)
        : "r"(a0), "r"(a1), "r"(a2), "r"(a3), "r"(b0), "r"(b1));
}

__device__ __forceinline__ uint32_t pack_h2(float a, float b) {
    __half2 h = __floats2half2_rn(a, b);
    return *(uint32_t*)&h;
}

// ------------- all weights fp32 -> fp16 in ONE launch -----------------------
#define S_IN  ((int)(2 * DINNER * DMODEL / 4))   // 1,048,576 float4s
#define S_XP  ((int)(NDBL * DINNER / 4))         //    49,152
#define S_DT  ((int)(DINNER * DTRANK / 4))       //    32,768
#define S_OP  ((int)(DMODEL * DINNER / 4))       //   524,288
#define S_ALL (S_IN + S_XP + S_DT + S_OP)

__global__ __launch_bounds__(256) void w2h_all_kernel(
    const float4* __restrict__ win, const float4* __restrict__ wxp,
    const float4* __restrict__ wdt, const float4* __restrict__ wop,
    uint2* __restrict__ owin, uint2* __restrict__ owxp,
    uint2* __restrict__ owdt, uint2* __restrict__ owop)
{
    int i = blockIdx.x * blockDim.x + threadIdx.x;
    if (i >= S_ALL) return;
    const float4* src; uint2* dst; int j;
    if (i < S_IN)                    { src = win; dst = owin; j = i; }
    else if (i < S_IN + S_XP)        { src = wxp; dst = owxp; j = i - S_IN; }
    else if (i < S_IN + S_XP + S_DT) { src = wdt; dst = owdt; j = i - S_IN - S_XP; }
    else                             { src = wop; dst = owop; j = i - S_IN - S_XP - S_DT; }
    float4 v = src[j];
    dst[j] = make_uint2(pack_h2(v.x, v.y), pack_h2(v.z, v.w));
}

// ---------------- FP16 tensor-core GEMM: C[m,n] = sum_k A[m,k] * W[n,k] ----
// CTA: 128x128x64, 256 threads, 8 warps (2 M x 4 N), warp 64x32.
// 3-stage cp.async pipeline, one __syncthreads per 64-k iter, ldmatrix frags.
// EPI: 0 = plain fp32 store, 1 = softplus(c + bias[n]).
// Split-K via gridDim.z.
#define ROWB 144                            // bytes per smem row (128 data + 16 pad)
#define TILE_B (128 * ROWB)                 // 18432
#define STAGE_B (2 * TILE_B)                // A + B
#define MM_SMEM_BYTES (3 * STAGE_B)         // 110592

__device__ __forceinline__ void stage_tile(
    uint32_t sA, uint32_t sB,
    const __half* __restrict__ A, int lda,
    const __half* __restrict__ W, int ldw, int Nw,
    int m0, int n0, int k0, int tid)
{
    #pragma unroll
    for (int i = 0; i < 4; i++) {
        int idx = i * 256 + tid;            // 0..1023
        int row = idx >> 3;
        int c   = idx & 7;                  // 16B chunk (8 halfs)
        cp16(sA + (uint32_t)(row * ROWB + c * 16),
             &A[(size_t)(m0 + row) * lda + k0 + c * 8]);
    }
    #pragma unroll
    for (int i = 0; i < 4; i++) {
        int idx = i * 256 + tid;
        int row = idx >> 3;
        int c   = idx & 7;
        int n = n0 + row;
        int nn = (n < Nw) ? n : 0;          // clamp; garbage cols never stored
        cp16(sB + (uint32_t)(row * ROWB + c * 16),
             &W[(size_t)nn * ldw + k0 + c * 8]);
    }
}

template <int EPI>
__global__ __launch_bounds__(256, 2) void mm_f16(
    const __half* __restrict__ A, int lda,
    const __half* __restrict__ W, int Nw,     // valid W rows
    const float* __restrict__ bias,
    float* __restrict__ C, int ldc, int Nc,   // valid C cols
    int K,                                     // K per z-slice (multiple of 64)
    size_t cSlice)                             // C offset per z-slice
{
    extern __shared__ char smem_c[];
    const uint32_t sbase = smem_u32(smem_c);
    const int tid  = threadIdx.x;
    const int wid  = tid >> 5;
    const int lane = tid & 31;
    const int g    = lane >> 2;
    const int t4   = lane & 3;
    const int wm   = wid >> 2;                // 0..1
    const int wn   = wid & 3;                 // 0..3
    const int mW   = wm * 64;
    const int nW   = wn * 32;
    const int m0 = blockIdx.y * 128;
    const int n0 = blockIdx.x * 128;
    const int kBase = blockIdx.z * K;
    const int iters = K / 64;

    C += (size_t)blockIdx.z * cSlice;
    const int ldw = K * gridDim.z;

    const uint32_t offA = (uint32_t)((mW + (lane & 15)) * ROWB + (lane >> 4) * 16);
    const uint32_t offB = (uint32_t)((nW + (lane & 15)) * ROWB + (lane >> 4) * 16);

    float acc[4][4][4];
    #pragma unroll
    for (int i = 0; i < 4; i++)
        #pragma unroll
        for (int j = 0; j < 4; j++)
            #pragma unroll
            for (int q = 0; q < 4; q++) acc[i][j][q] = 0.0f;

    // prologue: stage tiles 0 and 1 (clamped when iters == 1)
    stage_tile(sbase, sbase + TILE_B, A, lda, W, ldw, Nw, m0, n0, kBase, tid);
    cp_commit();
    {
        int k1 = (iters > 1) ? kBase + 64 : kBase;
        stage_tile(sbase + STAGE_B, sbase + STAGE_B + TILE_B,
                   A, lda, W, ldw, Nw, m0, n0, k1, tid);
    }
    cp_commit();

    for (int it = 0; it < iters; it++) {
        cp_wait<1>();
        __syncthreads();

        if (it + 2 < iters) {
            int s = (it + 2) % 3;
            stage_tile(sbase + (uint32_t)s * STAGE_B,
                       sbase + (uint32_t)s * STAGE_B + TILE_B,
                       A, lda, W, ldw, Nw, m0, n0, kBase + (it + 2) * 64, tid);
        }
        cp_commit();

        const uint32_t aBase = sbase + (uint32_t)(it % 3) * STAGE_B;
        const uint32_t bBase = aBase + TILE_B;

        #pragma unroll
        for (int ks = 0; ks < 4; ks++) {       // four k16 steps per 64-k tile
            uint32_t b0r[4], b1r[4];
            ldsm_x4(b0r[0], b0r[1], b0r[2], b0r[3], bBase + offB + ks * 32);
            ldsm_x4(b1r[0], b1r[1], b1r[2], b1r[3],
                    bBase + offB + 16 * ROWB + ks * 32);
            #pragma unroll
            for (int i = 0; i < 4; i++) {
                uint32_t a0, a1, a2, a3;
                ldsm_x4(a0, a1, a2, a3,
                        aBase + offA + (uint32_t)(i * 16 * ROWB) + ks * 32);
                mma_f16(acc[i][0][0], acc[i][0][1], acc[i][0][2], acc[i][0][3],
                        a0, a1, a2, a3, b0r[0], b0r[2]);
                mma_f16(acc[i][1][0], acc[i][1][1], acc[i][1][2], acc[i][1][3],
                        a0, a1, a2, a3, b0r[1], b0r[3]);
                mma_f16(acc[i][2][0], acc[i][2][1], acc[i][2][2], acc[i][2][3],
                        a0, a1, a2, a3, b1r[0], b1r[2]);
                mma_f16(acc[i][3][0], acc[i][3][1], acc[i][3][2], acc[i][3][3],
                        a0, a1, a2, a3, b1r[1], b1r[3]);
            }
        }
    }

    // ---- epilogue: registers -> global (float2 stores, 32B coalesced) ----
    #pragma unroll
    for (int i = 0; i < 4; i++) {
        #pragma unroll
        for (int j = 0; j < 4; j++) {
            int col = n0 + nW + j * 8 + t4 * 2;
            if (col < Nc) {
                int row0 = m0 + mW + i * 16 + g;
                float2 v0 = make_float2(acc[i][j][0], acc[i][j][1]);
                float2 v1 = make_float2(acc[i][j][2], acc[i][j][3]);
                if (EPI == 1) {
                    v0.x = softplusf(v0.x + bias[col]);
                    v0.y = softplusf(v0.y + bias[col + 1]);
                    v1.x = softplusf(v1.x + bias[col]);
                    v1.y = softplusf(v1.y + bias[col + 1]);
                }
                *(float2*)&C[(size_t)row0 * ldc + col]       = v0;
                *(float2*)&C[(size_t)(row0 + 8) * ldc + col] = v1;
            }
        }
    }
}

// ---------------- split-K partial reduce ------------------------------------
__global__ __launch_bounds__(256) void reduce_splits_kernel(
    const float* __restrict__ part, float* __restrict__ out,
    __half* __restrict__ dtlow, int n4)
{
    int i = blockIdx.x * blockDim.x + threadIdx.x;
    if (i >= n4) return;
    const float4* p = (const float4*)part;
    float4 s = p[i];
    #pragma unroll
    for (int k = 1; k < XP_SPLITS; k++) {
        float4 v = p[(size_t)k * n4 + i];
        s.x += v.x; s.y += v.y; s.z += v.z; s.w += v.w;
    }
    int cq = i % (NDBL / 4);
    if (cq < (DTRANK / 4)) {
        int row = i / (NDBL / 4);
        *(uint2*)&dtlow[(size_t)row * DTRANK + cq * 4] =
            make_uint2(pack_h2(s.x, s.y), pack_h2(s.z, s.w));
    } else {
        ((float4*)out)[i] = s;
    }
}

// ------- 1) add + rmsnorm -> fp16 -------------------------------------------
__global__ __launch_bounds__(256) void addnorm_kernel(
    const float* __restrict__ hs,
    const float* __restrict__ res,
    const float* __restrict__ w,
    __half* __restrict__ out)
{
    int row = blockIdx.x;
    int tid = threadIdx.x;
    const float4* a4 = (const float4*)(hs  + (size_t)row * DMODEL);
    const float4* b4 = (const float4*)(res + (size_t)row * DMODEL);
    const float4* w4 = (const float4*)w;
    float4 v = a4[tid];
    float4 b = b4[tid];
    v.x += b.x; v.y += b.y; v.z += b.z; v.w += b.w;
    float ss = v.x*v.x + v.y*v.y + v.z*v.z + v.w*v.w;

    __shared__ float red[8];
    #pragma unroll
    for (int off = 16; off > 0; off >>= 1)
        ss += __shfl_xor_sync(0xffffffffu, ss, off);
    if ((tid & 31) == 0) red[tid >> 5] = ss;
    __syncthreads();
    if (tid < 32) {
        float s = (tid < 8) ? red[tid] : 0.0f;
        #pragma unroll
        for (int off = 4; off > 0; off >>= 1)
            s += __shfl_xor_sync(0xffffffffu, s, off);
        if (tid == 0) red[0] = s;
    }
    __syncthreads();
    float rstd = rsqrtf(red[0] * (1.0f / DMODEL) + 1e-5f);

    float4 ww = w4[tid];
    *(uint2*)&out[(size_t)row * DMODEL + tid * 4] =
        make_uint2(pack_h2(v.x * rstd * ww.x, v.y * rstd * ww.y),
                   pack_h2(v.z * rstd * ww.z, v.w * rstd * ww.w));
}

// ------- 3) causal depthwise conv + bias + SiLU -> fp32 + fp16 --------------
__global__ __launch_bounds__(256) void conv_silu_kernel(
    const float* __restrict__ xz,
    const float* __restrict__ cw,
    const float* __restrict__ cb,
    float* __restrict__ xc,
    __half* __restrict__ xch)
{
    int idx = blockIdx.x * blockDim.x + threadIdx.x;
    int dq = idx & (DINNER / 4 - 1);
    int t  = idx / (DINNER / 4);
    int d  = dq * 4;
    int l  = t & (LSEQ - 1);

    float4 bias4 = *(const float4*)&cb[d];
    float acc0 = bias4.x, acc1 = bias4.y, acc2 = bias4.z, acc3 = bias4.w;

    float4 w0 = *(const float4*)&cw[(d + 0) * 4];
    float4 w1 = *(const float4*)&cw[(d + 1) * 4];
    float4 w2 = *(const float4*)&cw[(d + 2) * 4];
    float4 w3 = *(const float4*)&cw[(d + 3) * 4];
    float wv0[4] = {w0.x, w0.y, w0.z, w0.w};
    float wv1[4] = {w1.x, w1.y, w1.z, w1.w};
    float wv2[4] = {w2.x, w2.y, w2.z, w2.w};
    float wv3[4] = {w3.x, w3.y, w3.z, w3.w};

    #pragma unroll
    for (int j = 0; j < 4; j++) {
        int lsrc = l - 3 + j;
        if (lsrc >= 0) {
            float4 v = *(const float4*)&xz[(size_t)(t - 3 + j) * (2 * DINNER) + d];
            acc0 = fmaf(v.x, wv0[j], acc0);
            acc1 = fmaf(v.y, wv1[j], acc1);
            acc2 = fmaf(v.z, wv2[j], acc2);
            acc3 = fmaf(v.w, wv3[j], acc3);
        }
    }
    float4 o;
    o.x = siluf(acc0); o.y = siluf(acc1); o.z = siluf(acc2); o.w = siluf(acc3);
    *(float4*)&xc[(size_t)t * DINNER + d] = o;
    *(uint2*)&xch[(size_t)t * DINNER + d] =
        make_uint2(pack_h2(o.x, o.y), pack_h2(o.z, o.w));
}

// ------- 4) selective scan -> y fp16 -----------------------------------------
__global__ __launch_bounds__(256) void scan_kernel(
    const float* __restrict__ dt,
    const float* __restrict__ xz,
    const float* __restrict__ xc,
    const float* __restrict__ xdbl,
    const float* __restrict__ A_log,
    const float* __restrict__ Dp,
    __half* __restrict__ y)
{
    const int CH = 64;
    __shared__ float sdt[CH][16], sx[CH][16], sz[CH][16];
    __shared__ float sB[CH][16], sC[CH][16], sy[CH][16];

    int b  = blockIdx.x >> 7;
    int d0 = (blockIdx.x & 127) * 16;
    int tid = threadIdx.x;
    int c = tid >> 4;
    int n = tid & 15;
    int d = d0 + c;

    float Acoef = -expf(A_log[d * DSTATE + n]);
    float h = 0.0f;

    int e  = tid * 4;
    int le = e >> 4;
    int ie = e & 15;

    for (int l0 = 0; l0 < LSEQ; l0 += CH) {
        {
            size_t t = (size_t)b * LSEQ + l0 + le;
            *(float4*)&sdt[le][ie] = *(const float4*)&dt[t * DINNER + d0 + ie];
            *(float4*)&sx [le][ie] = *(const float4*)&xc[t * DINNER + d0 + ie];
            *(float4*)&sz [le][ie] = *(const float4*)&xz[t * (2 * DINNER) + DINNER + d0 + ie];
            *(float4*)&sB [le][ie] = *(const float4*)&xdbl[t * NDBL + DTRANK + ie];
            *(float4*)&sC [le][ie] = *(const float4*)&xdbl[t * NDBL + DTRANK + DSTATE + ie];
        }
        __syncthreads();

        #pragma unroll 4
        for (int ll = 0; ll < CH; ll++) {
            float dtv = sdt[ll][c];
            float xv  = sx[ll][c];
            float ea  = __expf(dtv * Acoef);
            h = fmaf(ea, h, dtv * xv * sB[ll][n]);
            float p = h * sC[ll][n];
            p += __shfl_xor_sync(0xffffffffu, p, 8);
            p += __shfl_xor_sync(0xffffffffu, p, 4);
            p += __shfl_xor_sync(0xffffffffu, p, 2);
            p += __shfl_xor_sync(0xffffffffu, p, 1);
            if (n == 0) sy[ll][c] = p;
        }
        __syncthreads();

        {
            size_t t = (size_t)b * LSEQ + l0 + le;
            float4 ys = *(float4*)&sy[le][ie];
            float4 xs = *(float4*)&sx[le][ie];
            float4 zs = *(float4*)&sz[le][ie];
            float4 dd = *(const float4*)&Dp[d0 + ie];
            float o0 = (ys.x + xs.x * dd.x) * siluf(zs.x);
            float o1 = (ys.y + xs.y * dd.y) * siluf(zs.y);
            float o2 = (ys.z + xs.z * dd.z) * siluf(zs.z);
            float o3 = (ys.w + xs.w * dd.w) * siluf(zs.w);
            *(uint2*)&y[t * DINNER + d0 + ie] =
                make_uint2(pack_h2(o0, o1), pack_h2(o2, o3));
        }
        __syncthreads();
    }
}

// ---------------- launcher ----------------
extern "C" void kernel_launch(void* const* d_in, const int* in_sizes, int n_in,
                              void* d_out, int out_size)
{
    (void)in_sizes; (void)n_in; (void)out_size;
    const float* hs        = (const float*)d_in[1];
    const float* residual  = (const float*)d_in[2];
    const float* norm_w    = (const float*)d_in[3];
    const float* in_proj_w = (const float*)d_in[4];
    const float* conv_w    = (const float*)d_in[5];
    const float* conv_b    = (const float*)d_in[6];
    const float* x_proj_w  = (const float*)d_in[7];
    const float* dt_proj_w = (const float*)d_in[8];
    const float* dt_proj_b = (const float*)d_in[9];
    const float* A_log     = (const float*)d_in[10];
    const float* D_param   = (const float*)d_in[11];
    const float* out_proj_w= (const float*)d_in[12];
    float* out = (float*)d_out;

    static float* scratch = nullptr;
    if (!scratch) {
        void* p = nullptr;
        cudaGetSymbolAddress(&p, g_scratch);
        scratch = (float*)p;
        cudaFuncSetAttribute(mm_f16<0>, cudaFuncAttributeMaxDynamicSharedMemorySize, MM_SMEM_BYTES);
        cudaFuncSetAttribute(mm_f16<1>, cudaFuncAttributeMaxDynamicSharedMemorySize, MM_SMEM_BYTES);
    }
    float*  g_xz   = scratch + OFF_XZ;
    float*  g_xc   = scratch + OFF_XC;
    float*  g_xdbl = scratch + OFF_XDBL;
    float*  g_dt   = scratch + OFF_DT;
    float*  g_xp   = scratch + OFF_XP;
    __half* g_h2   = (__half*)(scratch + OFF_H2);
    __half* g_xch  = (__half*)(scratch + OFF_XCH);
    __half* g_dtl  = (__half*)(scratch + OFF_DTL);
    __half* g_y2   = (__half*)(scratch + OFF_Y2);
    __half* g_win  = (__half*)(scratch + OFF_WIN2);
    __half* g_wxp  = (__half*)(scratch + OFF_WXP2);
    __half* g_wdt  = (__half*)(scratch + OFF_WDT2);
    __half* g_wop  = (__half*)(scratch + OFF_WOP2);

    // 0) all weights fp32 -> fp16 in one launch
    w2h_all_kernel<<<(S_ALL + 255) / 256, 256>>>(
        (const float4*)in_proj_w, (const float4*)x_proj_w,
        (const float4*)dt_proj_w, (const float4*)out_proj_w,
        (uint2*)g_win, (uint2*)g_wxp, (uint2*)g_wdt, (uint2*)g_wop);

    // 1) h = fp16(rmsnorm(hidden + residual) * w)
    addnorm_kernel<<<NTOK, 256>>>(hs, residual, norm_w, g_h2);

    // 2) xz = h @ in_proj_w^T   [4096 x 4096], K=1024
    mm_f16<0><<<dim3(4096 / 128, NTOK / 128, 1), 256, MM_SMEM_BYTES>>>(
        g_h2, DMODEL, g_win, 2 * DINNER, nullptr,
        g_xz, 2 * DINNER, 2 * DINNER, DMODEL, 0);

    // 3) xc = silu(causal_conv(x) + b)  -> fp32 (scan) + fp16 (x_proj)
    conv_silu_kernel<<<(NTOK * DINNER / 4) / 256, 256>>>(
        g_xz, conv_w, conv_b, g_xc, g_xch);

    // 4) x_dbl partials = xc @ x_proj_w^T   [4096 x 96], K=2048, split-K=8
    mm_f16<0><<<dim3(1, NTOK / 128, XP_SPLITS), 256, MM_SMEM_BYTES>>>(
        g_xch, DINNER, g_wxp, NDBL, nullptr,
        g_xp, NDBL, NDBL, DINNER / XP_SPLITS, (size_t)NTOK * NDBL);
    reduce_splits_kernel<<<(NTOK * NDBL / 4 + 255) / 256, 256>>>(
        g_xp, g_xdbl, g_dtl, NTOK * NDBL / 4);

    // 5) dt = softplus(dtlow @ dt_proj_w^T + b)   [4096 x 2048], K=64
    mm_f16<1><<<dim3(DINNER / 128, NTOK / 128, 1), 256, MM_SMEM_BYTES>>>(
        g_dtl, DTRANK, g_wdt, DINNER, dt_proj_b,
        g_dt, DINNER, DINNER, DTRANK, 0);

    // 6) selective scan + gate -> y (fp16 for out_proj)
    scan_kernel<<<BATCH * (DINNER / 16), 256>>>(
        g_dt, g_xz, g_xc, g_xdbl, A_log, D_param, g_y2);

    // 7) out = y @ out_proj_w^T   [4096 x 1024], K=2048
    mm_f16<0><<<dim3(DMODEL / 128, NTOK / 128, 1), 256, MM_SMEM_BYTES>>>(
        g_y2, DINNER, g_wop, DMODEL, nullptr,
        out, DMODEL, DMODEL, DINNER, 0);
}

// round 11
// speedup vs baseline: 2.2347x; 1.0364x over previous
#include <cuda_runtime.h>
#include <cuda_fp16.h>
#include <cstdint>

// ---------------- Problem constants ----------------
#define BATCH   2
#define LSEQ    2048
#define NTOK    (BATCH * LSEQ)      // 4096 tokens
#define DMODEL  1024
#define DINNER  2048
#define DSTATE  16
#define DCONV   4
#define DTRANK  64
#define NDBL    (DTRANK + 2 * DSTATE)   // 96
#define XP_SPLITS 8

// ---------------- Scratch (device globals; no allocation allowed) ----------
// fp32 regions (sizes in floats)
#define OFF_XZ    ((size_t)0)                                   // NTOK*4096
#define OFF_XC    (OFF_XZ   + (size_t)NTOK * 2 * DINNER)        // NTOK*2048
#define OFF_XDBL  (OFF_XC   + (size_t)NTOK * DINNER)            // NTOK*96
#define OFF_DT    (OFF_XDBL + (size_t)NTOK * NDBL)              // NTOK*2048
#define OFF_XP    (OFF_DT   + (size_t)NTOK * DINNER)            // 8*NTOK*96
// half regions (sizes in floats = halfs/2)
#define OFF_H2    (OFF_XP   + (size_t)XP_SPLITS * NTOK * NDBL)
#define OFF_XCH   (OFF_H2   + (size_t)NTOK * DMODEL / 2)
#define OFF_DTL   (OFF_XCH  + (size_t)NTOK * DINNER / 2)
#define OFF_Y2    (OFF_DTL  + (size_t)NTOK * DTRANK / 2)
#define OFF_WIN2  (OFF_Y2   + (size_t)NTOK * DINNER / 2)
#define OFF_WXP2  (OFF_WIN2 + (size_t)2 * DINNER * DMODEL / 2)
#define OFF_WDT2  (OFF_WXP2 + (size_t)NDBL * DINNER / 2)
#define OFF_WOP2  (OFF_WDT2 + (size_t)DINNER * DTRANK / 2)
#define SCRATCH_FLOATS (OFF_WOP2 + (size_t)DMODEL * DINNER / 2)

__device__ float g_scratch[SCRATCH_FLOATS];

// ---------------- helpers ----------------
__device__ __forceinline__ float siluf(float z) {
    return z * (1.0f / (1.0f + __expf(-z)));
}
__device__ __forceinline__ float softplusf(float v) {
    return fmaxf(v, 0.0f) + log1pf(expf(-fabsf(v)));
}

__device__ __forceinline__ uint32_t smem_u32(const void* p) {
    uint32_t addr;
    asm("{ .reg .u64 tmp; cvta.to.shared.u64 tmp, %1; cvt.u32.u64 %0, tmp; }"
        : "=r"(addr) : "l"(p));
    return addr;
}

__device__ __forceinline__ void cp16(uint32_t dst, const void* src) {
    asm volatile("cp.async.cg.shared.global [%0], [%1], 16;" :: "r"(dst), "l"(src));
}
__device__ __forceinline__ void cp_commit() {
    asm volatile("cp.async.commit_group;");
}
template <int N>
__device__ __forceinline__ void cp_wait() {
    asm volatile("cp.async.wait_group %0;" :: "n"(N));
}

__device__ __forceinline__ void ldsm_x4(
    uint32_t& r0, uint32_t& r1, uint32_t& r2, uint32_t& r3, uint32_t addr)
{
    asm volatile(
        "ldmatrix.sync.aligned.m8n8.x4.shared.b16 {%0,%1,%2,%3}, [%4];"
        : "=r"(r0), "=r"(r1), "=r"(r2), "=r"(r3) : "r"(addr));
}

// D(16x8) += A(16x16) * B(16x8), f16 inputs, f32 accumulate
__device__ __forceinline__ void mma_f16(
    float& c0, float& c1, float& c2, float& c3,
    uint32_t a0, uint32_t a1, uint32_t a2, uint32_t a3,
    uint32_t b0, uint32_t b1)
{
    asm volatile(
        "mma.sync.aligned.m16n8k16.row.col.f32.f16.f16.f32 "
        "{%0,%1,%2,%3}, {%4,%5,%6,%7}, {%8,%9}, {%0,%1,%2,%3};"
        : "+f"(c0), "+f"(c1), "+f"(c2), "+f"(c3)
        : "r"(a0), "r"(a1), "r"(a2), "r"(a3), "r"(b0), "r"(b1));
}

__device__ __forceinline__ uint32_t pack_h2(float a, float b) {
    __half2 h = __floats2half2_rn(a, b);
    return *(uint32_t*)&h;
}

// ------------- all weights fp32 -> fp16 in ONE launch -----------------------
#define S_IN  ((int)(2 * DINNER * DMODEL / 4))   // 1,048,576 float4s
#define S_XP  ((int)(NDBL * DINNER / 4))         //    49,152
#define S_DT  ((int)(DINNER * DTRANK / 4))       //    32,768
#define S_OP  ((int)(DMODEL * DINNER / 4))       //   524,288
#define S_ALL (S_IN + S_XP + S_DT + S_OP)

__global__ __launch_bounds__(256) void w2h_all_kernel(
    const float4* __restrict__ win, const float4* __restrict__ wxp,
    const float4* __restrict__ wdt, const float4* __restrict__ wop,
    uint2* __restrict__ owin, uint2* __restrict__ owxp,
    uint2* __restrict__ owdt, uint2* __restrict__ owop)
{
    int i = blockIdx.x * blockDim.x + threadIdx.x;
    if (i >= S_ALL) return;
    const float4* src; uint2* dst; int j;
    if (i < S_IN)                    { src = win; dst = owin; j = i; }
    else if (i < S_IN + S_XP)        { src = wxp; dst = owxp; j = i - S_IN; }
    else if (i < S_IN + S_XP + S_DT) { src = wdt; dst = owdt; j = i - S_IN - S_XP; }
    else                             { src = wop; dst = owop; j = i - S_IN - S_XP - S_DT; }
    float4 v = src[j];
    dst[j] = make_uint2(pack_h2(v.x, v.y), pack_h2(v.z, v.w));
}

// ---------------- FP16 tensor-core GEMM: C[m,n] = sum_k A[m,k] * W[n,k] ----
// CTA: 128x128x64, 256 threads, 8 warps (2 M x 4 N), warp 64x32.
// 3-stage cp.async pipeline, one __syncthreads per 64-k iter, ldmatrix frags.
// EPI: 0 = plain fp32 store, 1 = softplus(c + bias[n]).
// Split-K via gridDim.z.
#define ROWB 144                            // bytes per smem row (128 data + 16 pad)
#define TILE_B (128 * ROWB)                 // 18432
#define STAGE_B (2 * TILE_B)                // A + B
#define MM_SMEM_BYTES (3 * STAGE_B)         // 110592

__device__ __forceinline__ void stage_tile(
    uint32_t sA, uint32_t sB,
    const __half* __restrict__ A, int lda,
    const __half* __restrict__ W, int ldw, int Nw,
    int m0, int n0, int k0, int tid)
{
    #pragma unroll
    for (int i = 0; i < 4; i++) {
        int idx = i * 256 + tid;            // 0..1023
        int row = idx >> 3;
        int c   = idx & 7;                  // 16B chunk (8 halfs)
        cp16(sA + (uint32_t)(row * ROWB + c * 16),
             &A[(size_t)(m0 + row) * lda + k0 + c * 8]);
    }
    #pragma unroll
    for (int i = 0; i < 4; i++) {
        int idx = i * 256 + tid;
        int row = idx >> 3;
        int c   = idx & 7;
        int n = n0 + row;
        int nn = (n < Nw) ? n : 0;          // clamp; garbage cols never stored
        cp16(sB + (uint32_t)(row * ROWB + c * 16),
             &W[(size_t)nn * ldw + k0 + c * 8]);
    }
}

template <int EPI>
__global__ __launch_bounds__(256, 2) void mm_f16(
    const __half* __restrict__ A, int lda,
    const __half* __restrict__ W, int Nw,     // valid W rows
    const float* __restrict__ bias,
    float* __restrict__ C, int ldc, int Nc,   // valid C cols
    int K,                                     // K per z-slice (multiple of 64)
    size_t cSlice)                             // C offset per z-slice
{
    extern __shared__ char smem_c[];
    const uint32_t sbase = smem_u32(smem_c);
    const int tid  = threadIdx.x;
    const int wid  = tid >> 5;
    const int lane = tid & 31;
    const int g    = lane >> 2;
    const int t4   = lane & 3;
    const int wm   = wid >> 2;                // 0..1
    const int wn   = wid & 3;                 // 0..3
    const int mW   = wm * 64;
    const int nW   = wn * 32;
    const int m0 = blockIdx.y * 128;
    const int n0 = blockIdx.x * 128;
    const int kBase = blockIdx.z * K;
    const int iters = K / 64;

    C += (size_t)blockIdx.z * cSlice;
    const int ldw = K * gridDim.z;

    const uint32_t offA = (uint32_t)((mW + (lane & 15)) * ROWB + (lane >> 4) * 16);
    const uint32_t offB = (uint32_t)((nW + (lane & 15)) * ROWB + (lane >> 4) * 16);

    float acc[4][4][4];
    #pragma unroll
    for (int i = 0; i < 4; i++)
        #pragma unroll
        for (int j = 0; j < 4; j++)
            #pragma unroll
            for (int q = 0; q < 4; q++) acc[i][j][q] = 0.0f;

    // prologue: stage tiles 0 and 1 (clamped when iters == 1)
    stage_tile(sbase, sbase + TILE_B, A, lda, W, ldw, Nw, m0, n0, kBase, tid);
    cp_commit();
    {
        int k1 = (iters > 1) ? kBase + 64 : kBase;
        stage_tile(sbase + STAGE_B, sbase + STAGE_B + TILE_B,
                   A, lda, W, ldw, Nw, m0, n0, k1, tid);
    }
    cp_commit();

    for (int it = 0; it < iters; it++) {
        cp_wait<1>();
        __syncthreads();

        if (it + 2 < iters) {
            int s = (it + 2) % 3;
            stage_tile(sbase + (uint32_t)s * STAGE_B,
                       sbase + (uint32_t)s * STAGE_B + TILE_B,
                       A, lda, W, ldw, Nw, m0, n0, kBase + (it + 2) * 64, tid);
        }
        cp_commit();

        const uint32_t aBase = sbase + (uint32_t)(it % 3) * STAGE_B;
        const uint32_t bBase = aBase + TILE_B;

        #pragma unroll
        for (int ks = 0; ks < 4; ks++) {       // four k16 steps per 64-k tile
            uint32_t b0r[4], b1r[4];
            ldsm_x4(b0r[0], b0r[1], b0r[2], b0r[3], bBase + offB + ks * 32);
            ldsm_x4(b1r[0], b1r[1], b1r[2], b1r[3],
                    bBase + offB + 16 * ROWB + ks * 32);
            #pragma unroll
            for (int i = 0; i < 4; i++) {
                uint32_t a0, a1, a2, a3;
                ldsm_x4(a0, a1, a2, a3,
                        aBase + offA + (uint32_t)(i * 16 * ROWB) + ks * 32);
                mma_f16(acc[i][0][0], acc[i][0][1], acc[i][0][2], acc[i][0][3],
                        a0, a1, a2, a3, b0r[0], b0r[2]);
                mma_f16(acc[i][1][0], acc[i][1][1], acc[i][1][2], acc[i][1][3],
                        a0, a1, a2, a3, b0r[1], b0r[3]);
                mma_f16(acc[i][2][0], acc[i][2][1], acc[i][2][2], acc[i][2][3],
                        a0, a1, a2, a3, b1r[0], b1r[2]);
                mma_f16(acc[i][3][0], acc[i][3][1], acc[i][3][2], acc[i][3][3],
                        a0, a1, a2, a3, b1r[1], b1r[3]);
            }
        }
    }

    // ---- epilogue: registers -> global (float2 stores, 32B coalesced) ----
    #pragma unroll
    for (int i = 0; i < 4; i++) {
        #pragma unroll
        for (int j = 0; j < 4; j++) {
            int col = n0 + nW + j * 8 + t4 * 2;
            if (col < Nc) {
                int row0 = m0 + mW + i * 16 + g;
                float2 v0 = make_float2(acc[i][j][0], acc[i][j][1]);
                float2 v1 = make_float2(acc[i][j][2], acc[i][j][3]);
                if (EPI == 1) {
                    v0.x = softplusf(v0.x + bias[col]);
                    v0.y = softplusf(v0.y + bias[col + 1]);
                    v1.x = softplusf(v1.x + bias[col]);
                    v1.y = softplusf(v1.y + bias[col + 1]);
                }
                *(float2*)&C[(size_t)row0 * ldc + col]       = v0;
                *(float2*)&C[(size_t)(row0 + 8) * ldc + col] = v1;
            }
        }
    }
}

// ---------------- split-K partial reduce ------------------------------------
__global__ __launch_bounds__(256) void reduce_splits_kernel(
    const float* __restrict__ part, float* __restrict__ out,
    __half* __restrict__ dtlow, int n4)
{
    int i = blockIdx.x * blockDim.x + threadIdx.x;
    if (i >= n4) return;
    const float4* p = (const float4*)part;
    float4 s = p[i];
    #pragma unroll
    for (int k = 1; k < XP_SPLITS; k++) {
        float4 v = p[(size_t)k * n4 + i];
        s.x += v.x; s.y += v.y; s.z += v.z; s.w += v.w;
    }
    int cq = i % (NDBL / 4);
    if (cq < (DTRANK / 4)) {
        int row = i / (NDBL / 4);
        *(uint2*)&dtlow[(size_t)row * DTRANK + cq * 4] =
            make_uint2(pack_h2(s.x, s.y), pack_h2(s.z, s.w));
    } else {
        ((float4*)out)[i] = s;
    }
}

// ------- 1) add + rmsnorm -> fp16 -------------------------------------------
__global__ __launch_bounds__(256) void addnorm_kernel(
    const float* __restrict__ hs,
    const float* __restrict__ res,
    const float* __restrict__ w,
    __half* __restrict__ out)
{
    int row = blockIdx.x;
    int tid = threadIdx.x;
    const float4* a4 = (const float4*)(hs  + (size_t)row * DMODEL);
    const float4* b4 = (const float4*)(res + (size_t)row * DMODEL);
    const float4* w4 = (const float4*)w;
    float4 v = a4[tid];
    float4 b = b4[tid];
    v.x += b.x; v.y += b.y; v.z += b.z; v.w += b.w;
    float ss = v.x*v.x + v.y*v.y + v.z*v.z + v.w*v.w;

    __shared__ float red[8];
    #pragma unroll
    for (int off = 16; off > 0; off >>= 1)
        ss += __shfl_xor_sync(0xffffffffu, ss, off);
    if ((tid & 31) == 0) red[tid >> 5] = ss;
    __syncthreads();
    if (tid < 32) {
        float s = (tid < 8) ? red[tid] : 0.0f;
        #pragma unroll
        for (int off = 4; off > 0; off >>= 1)
            s += __shfl_xor_sync(0xffffffffu, s, off);
        if (tid == 0) red[0] = s;
    }
    __syncthreads();
    float rstd = rsqrtf(red[0] * (1.0f / DMODEL) + 1e-5f);

    float4 ww = w4[tid];
    *(uint2*)&out[(size_t)row * DMODEL + tid * 4] =
        make_uint2(pack_h2(v.x * rstd * ww.x, v.y * rstd * ww.y),
                   pack_h2(v.z * rstd * ww.z, v.w * rstd * ww.w));
}

// ------- 3) causal depthwise conv + bias + SiLU, register-blocked ----------
// Each thread: 4 consecutive timesteps x 4 channels. 7 row-loads -> 4 outputs.
__global__ __launch_bounds__(256) void conv_silu_kernel(
    const float* __restrict__ xz,
    const float* __restrict__ cw,
    const float* __restrict__ cb,
    float* __restrict__ xc,
    __half* __restrict__ xch)
{
    int idx = blockIdx.x * blockDim.x + threadIdx.x;   // over (NTOK/4)*(DINNER/4)
    int dq = idx & (DINNER / 4 - 1);
    int tq = idx / (DINNER / 4);
    int d  = dq * 4;
    int t0 = tq * 4;
    int l0 = t0 & (LSEQ - 1);          // 4-aligned; only l0==0 touches pad

    float4 bias4 = *(const float4*)&cb[d];
    float4 w0 = *(const float4*)&cw[(d + 0) * 4];
    float4 w1 = *(const float4*)&cw[(d + 1) * 4];
    float4 w2 = *(const float4*)&cw[(d + 2) * 4];
    float4 w3 = *(const float4*)&cw[(d + 3) * 4];
    float wv0[4] = {w0.x, w0.y, w0.z, w0.w};
    float wv1[4] = {w1.x, w1.y, w1.z, w1.w};
    float wv2[4] = {w2.x, w2.y, w2.z, w2.w};
    float wv3[4] = {w3.x, w3.y, w3.z, w3.w};

    // rows t0-3 .. t0+3 -> v[0..6]
    float4 v[7];
    #pragma unroll
    for (int k = 0; k < 7; k++) {
        if (l0 == 0 && k < 3) {
            v[k] = make_float4(0.f, 0.f, 0.f, 0.f);
        } else {
            v[k] = *(const float4*)&xz[(size_t)(t0 - 3 + k) * (2 * DINNER) + d];
        }
    }

    #pragma unroll
    for (int r = 0; r < 4; r++) {
        float a0 = bias4.x, a1 = bias4.y, a2 = bias4.z, a3 = bias4.w;
        #pragma unroll
        for (int j = 0; j < 4; j++) {
            float4 u = v[r + j];
            a0 = fmaf(u.x, wv0[j], a0);
            a1 = fmaf(u.y, wv1[j], a1);
            a2 = fmaf(u.z, wv2[j], a2);
            a3 = fmaf(u.w, wv3[j], a3);
        }
        float4 o;
        o.x = siluf(a0); o.y = siluf(a1); o.z = siluf(a2); o.w = siluf(a3);
        size_t t = (size_t)(t0 + r);
        *(float4*)&xc[t * DINNER + d] = o;
        *(uint2*)&xch[t * DINNER + d] =
            make_uint2(pack_h2(o.x, o.y), pack_h2(o.z, o.w));
    }
}

// ------- 4) selective scan -> y fp16 -----------------------------------------
__global__ __launch_bounds__(256) void scan_kernel(
    const float* __restrict__ dt,
    const float* __restrict__ xz,
    const float* __restrict__ xc,
    const float* __restrict__ xdbl,
    const float* __restrict__ A_log,
    const float* __restrict__ Dp,
    __half* __restrict__ y)
{
    const int CH = 64;
    __shared__ float sdt[CH][16], sx[CH][16], sz[CH][16];
    __shared__ float sB[CH][16], sC[CH][16], sy[CH][16];

    int b  = blockIdx.x >> 7;
    int d0 = (blockIdx.x & 127) * 16;
    int tid = threadIdx.x;
    int c = tid >> 4;
    int n = tid & 15;
    int d = d0 + c;

    float Acoef = -expf(A_log[d * DSTATE + n]);
    float h = 0.0f;

    int e  = tid * 4;
    int le = e >> 4;
    int ie = e & 15;

    for (int l0 = 0; l0 < LSEQ; l0 += CH) {
        {
            size_t t = (size_t)b * LSEQ + l0 + le;
            *(float4*)&sdt[le][ie] = *(const float4*)&dt[t * DINNER + d0 + ie];
            *(float4*)&sx [le][ie] = *(const float4*)&xc[t * DINNER + d0 + ie];
            *(float4*)&sz [le][ie] = *(const float4*)&xz[t * (2 * DINNER) + DINNER + d0 + ie];
            *(float4*)&sB [le][ie] = *(const float4*)&xdbl[t * NDBL + DTRANK + ie];
            *(float4*)&sC [le][ie] = *(const float4*)&xdbl[t * NDBL + DTRANK + DSTATE + ie];
        }
        __syncthreads();

        #pragma unroll 4
        for (int ll = 0; ll < CH; ll++) {
            float dtv = sdt[ll][c];
            float xv  = sx[ll][c];
            float ea  = __expf(dtv * Acoef);
            h = fmaf(ea, h, dtv * xv * sB[ll][n]);
            float p = h * sC[ll][n];
            p += __shfl_xor_sync(0xffffffffu, p, 8);
            p += __shfl_xor_sync(0xffffffffu, p, 4);
            p += __shfl_xor_sync(0xffffffffu, p, 2);
            p += __shfl_xor_sync(0xffffffffu, p, 1);
            if (n == 0) sy[ll][c] = p;
        }
        __syncthreads();

        {
            size_t t = (size_t)b * LSEQ + l0 + le;
            float4 ys = *(float4*)&sy[le][ie];
            float4 xs = *(float4*)&sx[le][ie];
            float4 zs = *(float4*)&sz[le][ie];
            float4 dd = *(const float4*)&Dp[d0 + ie];
            float o0 = (ys.x + xs.x * dd.x) * siluf(zs.x);
            float o1 = (ys.y + xs.y * dd.y) * siluf(zs.y);
            float o2 = (ys.z + xs.z * dd.z) * siluf(zs.z);
            float o3 = (ys.w + xs.w * dd.w) * siluf(zs.w);
            *(uint2*)&y[t * DINNER + d0 + ie] =
                make_uint2(pack_h2(o0, o1), pack_h2(o2, o3));
        }
        __syncthreads();
    }
}

// ---------------- launcher ----------------
extern "C" void kernel_launch(void* const* d_in, const int* in_sizes, int n_in,
                              void* d_out, int out_size)
{
    (void)in_sizes; (void)n_in; (void)out_size;
    const float* hs        = (const float*)d_in[1];
    const float* residual  = (const float*)d_in[2];
    const float* norm_w    = (const float*)d_in[3];
    const float* in_proj_w = (const float*)d_in[4];
    const float* conv_w    = (const float*)d_in[5];
    const float* conv_b    = (const float*)d_in[6];
    const float* x_proj_w  = (const float*)d_in[7];
    const float* dt_proj_w = (const float*)d_in[8];
    const float* dt_proj_b = (const float*)d_in[9];
    const float* A_log     = (const float*)d_in[10];
    const float* D_param   = (const float*)d_in[11];
    const float* out_proj_w= (const float*)d_in[12];
    float* out = (float*)d_out;

    static float* scratch = nullptr;
    if (!scratch) {
        void* p = nullptr;
        cudaGetSymbolAddress(&p, g_scratch);
        scratch = (float*)p;
        cudaFuncSetAttribute(mm_f16<0>, cudaFuncAttributeMaxDynamicSharedMemorySize, MM_SMEM_BYTES);
        cudaFuncSetAttribute(mm_f16<1>, cudaFuncAttributeMaxDynamicSharedMemorySize, MM_SMEM_BYTES);
    }
    float*  g_xz   = scratch + OFF_XZ;
    float*  g_xc   = scratch + OFF_XC;
    float*  g_xdbl = scratch + OFF_XDBL;
    float*  g_dt   = scratch + OFF_DT;
    float*  g_xp   = scratch + OFF_XP;
    __half* g_h2   = (__half*)(scratch + OFF_H2);
    __half* g_xch  = (__half*)(scratch + OFF_XCH);
    __half* g_dtl  = (__half*)(scratch + OFF_DTL);
    __half* g_y2   = (__half*)(scratch + OFF_Y2);
    __half* g_win  = (__half*)(scratch + OFF_WIN2);
    __half* g_wxp  = (__half*)(scratch + OFF_WXP2);
    __half* g_wdt  = (__half*)(scratch + OFF_WDT2);
    __half* g_wop  = (__half*)(scratch + OFF_WOP2);

    // 0) all weights fp32 -> fp16 in one launch
    w2h_all_kernel<<<(S_ALL + 255) / 256, 256>>>(
        (const float4*)in_proj_w, (const float4*)x_proj_w,
        (const float4*)dt_proj_w, (const float4*)out_proj_w,
        (uint2*)g_win, (uint2*)g_wxp, (uint2*)g_wdt, (uint2*)g_wop);

    // 1) h = fp16(rmsnorm(hidden + residual) * w)
    addnorm_kernel<<<NTOK, 256>>>(hs, residual, norm_w, g_h2);

    // 2) xz = h @ in_proj_w^T   [4096 x 4096], K=1024
    mm_f16<0><<<dim3(4096 / 128, NTOK / 128, 1), 256, MM_SMEM_BYTES>>>(
        g_h2, DMODEL, g_win, 2 * DINNER, nullptr,
        g_xz, 2 * DINNER, 2 * DINNER, DMODEL, 0);

    // 3) xc = silu(causal_conv(x) + b)  -> fp32 (scan) + fp16 (x_proj)
    conv_silu_kernel<<<(NTOK / 4) * (DINNER / 4) / 256, 256>>>(
        g_xz, conv_w, conv_b, g_xc, g_xch);

    // 4) x_dbl partials = xc @ x_proj_w^T   [4096 x 96], K=2048, split-K=8
    mm_f16<0><<<dim3(1, NTOK / 128, XP_SPLITS), 256, MM_SMEM_BYTES>>>(
        g_xch, DINNER, g_wxp, NDBL, nullptr,
        g_xp, NDBL, NDBL, DINNER / XP_SPLITS, (size_t)NTOK * NDBL);
    reduce_splits_kernel<<<(NTOK * NDBL / 4 + 255) / 256, 256>>>(
        g_xp, g_xdbl, g_dtl, NTOK * NDBL / 4);

    // 5) dt = softplus(dtlow @ dt_proj_w^T + b)   [4096 x 2048], K=64
    mm_f16<1><<<dim3(DINNER / 128, NTOK / 128, 1), 256, MM_SMEM_BYTES>>>(
        g_dtl, DTRANK, g_wdt, DINNER, dt_proj_b,
        g_dt, DINNER, DINNER, DTRANK, 0);

    // 6) selective scan + gate -> y (fp16 for out_proj)
    scan_kernel<<<BATCH * (DINNER / 16), 256>>>(
        g_dt, g_xz, g_xc, g_xdbl, A_log, D_param, g_y2);

    // 7) out = y @ out_proj_w^T   [4096 x 1024], K=2048
    mm_f16<0><<<dim3(DMODEL / 128, NTOK / 128, 1), 256, MM_SMEM_BYTES>>>(
        g_y2, DINNER, g_wop, DMODEL, nullptr,
        out, DMODEL, DMODEL, DINNER, 0);
}

// round 12
// speedup vs baseline: 2.2792x; 1.0199x over previous
#include <cuda_runtime.h>
#include <cuda_fp16.h>
#include <cstdint>

// ---------------- Problem constants ----------------
#define BATCH   2
#define LSEQ    2048
#define NTOK    (BATCH * LSEQ)      // 4096 tokens
#define DMODEL  1024
#define DINNER  2048
#define DSTATE  16
#define DCONV   4
#define DTRANK  64
#define NDBL    (DTRANK + 2 * DSTATE)   // 96
#define XP_SPLITS 8

// ---------------- Scratch (device globals; no allocation allowed) ----------
// fp32 regions (sizes in floats)
#define OFF_XC    ((size_t)0)                                   // NTOK*2048
#define OFF_XDBL  (OFF_XC   + (size_t)NTOK * DINNER)            // NTOK*96
#define OFF_DT    (OFF_XDBL + (size_t)NTOK * NDBL)              // NTOK*2048
#define OFF_XP    (OFF_DT   + (size_t)NTOK * DINNER)            // 8*NTOK*96
// half regions (sizes in floats = halfs/2)
#define OFF_XZH   (OFF_XP   + (size_t)XP_SPLITS * NTOK * NDBL)  // NTOK*4096/2
#define OFF_H2    (OFF_XZH  + (size_t)NTOK * 2 * DINNER / 2)
#define OFF_XCH   (OFF_H2   + (size_t)NTOK * DMODEL / 2)
#define OFF_DTL   (OFF_XCH  + (size_t)NTOK * DINNER / 2)
#define OFF_Y2    (OFF_DTL  + (size_t)NTOK * DTRANK / 2)
#define OFF_WIN2  (OFF_Y2   + (size_t)NTOK * DINNER / 2)
#define OFF_WXP2  (OFF_WIN2 + (size_t)2 * DINNER * DMODEL / 2)
#define OFF_WDT2  (OFF_WXP2 + (size_t)NDBL * DINNER / 2)
#define OFF_WOP2  (OFF_WDT2 + (size_t)DINNER * DTRANK / 2)
#define SCRATCH_FLOATS (OFF_WOP2 + (size_t)DMODEL * DINNER / 2)

__device__ float g_scratch[SCRATCH_FLOATS];

// ---------------- helpers ----------------
__device__ __forceinline__ float siluf(float z) {
    return z * (1.0f / (1.0f + __expf(-z)));
}
__device__ __forceinline__ float softplusf(float v) {
    return fmaxf(v, 0.0f) + log1pf(expf(-fabsf(v)));
}

__device__ __forceinline__ uint32_t smem_u32(const void* p) {
    uint32_t addr;
    asm("{ .reg .u64 tmp; cvta.to.shared.u64 tmp, %1; cvt.u32.u64 %0, tmp; }"
        : "=r"(addr) : "l"(p));
    return addr;
}

__device__ __forceinline__ void cp16(uint32_t dst, const void* src) {
    asm volatile("cp.async.cg.shared.global [%0], [%1], 16;" :: "r"(dst), "l"(src));
}
__device__ __forceinline__ void cp_commit() {
    asm volatile("cp.async.commit_group;");
}
template <int N>
__device__ __forceinline__ void cp_wait() {
    asm volatile("cp.async.wait_group %0;" :: "n"(N));
}

__device__ __forceinline__ void ldsm_x4(
    uint32_t& r0, uint32_t& r1, uint32_t& r2, uint32_t& r3, uint32_t addr)
{
    asm volatile(
        "ldmatrix.sync.aligned.m8n8.x4.shared.b16 {%0,%1,%2,%3}, [%4];"
        : "=r"(r0), "=r"(r1), "=r"(r2), "=r"(r3) : "r"(addr));
}

// D(16x8) += A(16x16) * B(16x8), f16 inputs, f32 accumulate
__device__ __forceinline__ void mma_f16(
    float& c0, float& c1, float& c2, float& c3,
    uint32_t a0, uint32_t a1, uint32_t a2, uint32_t a3,
    uint32_t b0, uint32_t b1)
{
    asm volatile(
        "mma.sync.aligned.m16n8k16.row.col.f32.f16.f16.f32 "
        "{%0,%1,%2,%3}, {%4,%5,%6,%7}, {%8,%9}, {%0,%1,%2,%3};"
        : "+f"(c0), "+f"(c1), "+f"(c2), "+f"(c3)
        : "r"(a0), "r"(a1), "r"(a2), "r"(a3), "r"(b0), "r"(b1));
}

__device__ __forceinline__ uint32_t pack_h2(float a, float b) {
    __half2 h = __floats2half2_rn(a, b);
    return *(uint32_t*)&h;
}
__device__ __forceinline__ float2 unpack_h2(uint32_t u) {
    __half2 h = *(__half2*)&u;
    return __half22float2(h);
}

// ------------- all weights fp32 -> fp16 in ONE launch -----------------------
#define S_IN  ((int)(2 * DINNER * DMODEL / 4))   // 1,048,576 float4s
#define S_XP  ((int)(NDBL * DINNER / 4))         //    49,152
#define S_DT  ((int)(DINNER * DTRANK / 4))       //    32,768
#define S_OP  ((int)(DMODEL * DINNER / 4))       //   524,288
#define S_ALL (S_IN + S_XP + S_DT + S_OP)

__global__ __launch_bounds__(256) void w2h_all_kernel(
    const float4* __restrict__ win, const float4* __restrict__ wxp,
    const float4* __restrict__ wdt, const float4* __restrict__ wop,
    uint2* __restrict__ owin, uint2* __restrict__ owxp,
    uint2* __restrict__ owdt, uint2* __restrict__ owop)
{
    int i = blockIdx.x * blockDim.x + threadIdx.x;
    if (i >= S_ALL) return;
    const float4* src; uint2* dst; int j;
    if (i < S_IN)                    { src = win; dst = owin; j = i; }
    else if (i < S_IN + S_XP)        { src = wxp; dst = owxp; j = i - S_IN; }
    else if (i < S_IN + S_XP + S_DT) { src = wdt; dst = owdt; j = i - S_IN - S_XP; }
    else                             { src = wop; dst = owop; j = i - S_IN - S_XP - S_DT; }
    float4 v = src[j];
    dst[j] = make_uint2(pack_h2(v.x, v.y), pack_h2(v.z, v.w));
}

// ---------------- FP16 tensor-core GEMM: C[m,n] = sum_k A[m,k] * W[n,k] ----
// CTA: 128x128x64, 256 threads, 8 warps (2 M x 4 N), warp 64x32.
// 3-stage cp.async pipeline, one __syncthreads per 64-k iter, ldmatrix frags.
// EPI: 0 = plain store, 1 = softplus(c + bias[n]) (fp32 out only).
// HOUT: store __half output instead of fp32.
#define ROWB 144                            // bytes per smem row (128 data + 16 pad)
#define TILE_B (128 * ROWB)                 // 18432
#define STAGE_B (2 * TILE_B)                // A + B
#define MM_SMEM_BYTES (3 * STAGE_B)         // 110592

__device__ __forceinline__ void stage_tile(
    uint32_t sA, uint32_t sB,
    const __half* __restrict__ A, int lda,
    const __half* __restrict__ W, int ldw, int Nw,
    int m0, int n0, int k0, int tid)
{
    #pragma unroll
    for (int i = 0; i < 4; i++) {
        int idx = i * 256 + tid;            // 0..1023
        int row = idx >> 3;
        int c   = idx & 7;                  // 16B chunk (8 halfs)
        cp16(sA + (uint32_t)(row * ROWB + c * 16),
             &A[(size_t)(m0 + row) * lda + k0 + c * 8]);
    }
    #pragma unroll
    for (int i = 0; i < 4; i++) {
        int idx = i * 256 + tid;
        int row = idx >> 3;
        int c   = idx & 7;
        int n = n0 + row;
        int nn = (n < Nw) ? n : 0;          // clamp; garbage cols never stored
        cp16(sB + (uint32_t)(row * ROWB + c * 16),
             &W[(size_t)nn * ldw + k0 + c * 8]);
    }
}

template <int EPI, bool HOUT>
__global__ __launch_bounds__(256, 2) void mm_f16(
    const __half* __restrict__ A, int lda,
    const __half* __restrict__ W, int Nw,     // valid W rows
    const float* __restrict__ bias,
    void* __restrict__ Cv, int ldc, int Nc,   // valid C cols
    int K,                                     // K per z-slice (multiple of 64)
    size_t cSlice)                             // C offset per z-slice (elements)
{
    extern __shared__ char smem_c[];
    const uint32_t sbase = smem_u32(smem_c);
    const int tid  = threadIdx.x;
    const int wid  = tid >> 5;
    const int lane = tid & 31;
    const int g    = lane >> 2;
    const int t4   = lane & 3;
    const int wm   = wid >> 2;                // 0..1
    const int wn   = wid & 3;                 // 0..3
    const int mW   = wm * 64;
    const int nW   = wn * 32;
    const int m0 = blockIdx.y * 128;
    const int n0 = blockIdx.x * 128;
    const int kBase = blockIdx.z * K;
    const int iters = K / 64;

    const size_t zoff = (size_t)blockIdx.z * cSlice;
    const int ldw = K * gridDim.z;

    const uint32_t offA = (uint32_t)((mW + (lane & 15)) * ROWB + (lane >> 4) * 16);
    const uint32_t offB = (uint32_t)((nW + (lane & 15)) * ROWB + (lane >> 4) * 16);

    float acc[4][4][4];
    #pragma unroll
    for (int i = 0; i < 4; i++)
        #pragma unroll
        for (int j = 0; j < 4; j++)
            #pragma unroll
            for (int q = 0; q < 4; q++) acc[i][j][q] = 0.0f;

    // prologue: stage tiles 0 and 1 (clamped when iters == 1)
    stage_tile(sbase, sbase + TILE_B, A, lda, W, ldw, Nw, m0, n0, kBase, tid);
    cp_commit();
    {
        int k1 = (iters > 1) ? kBase + 64 : kBase;
        stage_tile(sbase + STAGE_B, sbase + STAGE_B + TILE_B,
                   A, lda, W, ldw, Nw, m0, n0, k1, tid);
    }
    cp_commit();

    for (int it = 0; it < iters; it++) {
        cp_wait<1>();
        __syncthreads();

        if (it + 2 < iters) {
            int s = (it + 2) % 3;
            stage_tile(sbase + (uint32_t)s * STAGE_B,
                       sbase + (uint32_t)s * STAGE_B + TILE_B,
                       A, lda, W, ldw, Nw, m0, n0, kBase + (it + 2) * 64, tid);
        }
        cp_commit();

        const uint32_t aBase = sbase + (uint32_t)(it % 3) * STAGE_B;
        const uint32_t bBase = aBase + TILE_B;

        #pragma unroll
        for (int ks = 0; ks < 4; ks++) {       // four k16 steps per 64-k tile
            uint32_t b0r[4], b1r[4];
            ldsm_x4(b0r[0], b0r[1], b0r[2], b0r[3], bBase + offB + ks * 32);
            ldsm_x4(b1r[0], b1r[1], b1r[2], b1r[3],
                    bBase + offB + 16 * ROWB + ks * 32);
            #pragma unroll
            for (int i = 0; i < 4; i++) {
                uint32_t a0, a1, a2, a3;
                ldsm_x4(a0, a1, a2, a3,
                        aBase + offA + (uint32_t)(i * 16 * ROWB) + ks * 32);
                mma_f16(acc[i][0][0], acc[i][0][1], acc[i][0][2], acc[i][0][3],
                        a0, a1, a2, a3, b0r[0], b0r[2]);
                mma_f16(acc[i][1][0], acc[i][1][1], acc[i][1][2], acc[i][1][3],
                        a0, a1, a2, a3, b0r[1], b0r[3]);
                mma_f16(acc[i][2][0], acc[i][2][1], acc[i][2][2], acc[i][2][3],
                        a0, a1, a2, a3, b1r[0], b1r[2]);
                mma_f16(acc[i][3][0], acc[i][3][1], acc[i][3][2], acc[i][3][3],
                        a0, a1, a2, a3, b1r[1], b1r[3]);
            }
        }
    }

    // ---- epilogue: registers -> global ----
    #pragma unroll
    for (int i = 0; i < 4; i++) {
        #pragma unroll
        for (int j = 0; j < 4; j++) {
            int col = n0 + nW + j * 8 + t4 * 2;
            if (col < Nc) {
                int row0 = m0 + mW + i * 16 + g;
                float2 v0 = make_float2(acc[i][j][0], acc[i][j][1]);
                float2 v1 = make_float2(acc[i][j][2], acc[i][j][3]);
                if (EPI == 1) {
                    v0.x = softplusf(v0.x + bias[col]);
                    v0.y = softplusf(v0.y + bias[col + 1]);
                    v1.x = softplusf(v1.x + bias[col]);
                    v1.y = softplusf(v1.y + bias[col + 1]);
                }
                if (HOUT) {
                    __half* Ch = (__half*)Cv + zoff;
                    *(uint32_t*)&Ch[(size_t)row0 * ldc + col] = pack_h2(v0.x, v0.y);
                    *(uint32_t*)&Ch[(size_t)(row0 + 8) * ldc + col] = pack_h2(v1.x, v1.y);
                } else {
                    float* Cf = (float*)Cv + zoff;
                    *(float2*)&Cf[(size_t)row0 * ldc + col]       = v0;
                    *(float2*)&Cf[(size_t)(row0 + 8) * ldc + col] = v1;
                }
            }
        }
    }
}

// ---------------- split-K partial reduce ------------------------------------
__global__ __launch_bounds__(256) void reduce_splits_kernel(
    const float* __restrict__ part, float* __restrict__ out,
    __half* __restrict__ dtlow, int n4)
{
    int i = blockIdx.x * blockDim.x + threadIdx.x;
    if (i >= n4) return;
    const float4* p = (const float4*)part;
    float4 s = p[i];
    #pragma unroll
    for (int k = 1; k < XP_SPLITS; k++) {
        float4 v = p[(size_t)k * n4 + i];
        s.x += v.x; s.y += v.y; s.z += v.z; s.w += v.w;
    }
    int cq = i % (NDBL / 4);
    if (cq < (DTRANK / 4)) {
        int row = i / (NDBL / 4);
        *(uint2*)&dtlow[(size_t)row * DTRANK + cq * 4] =
            make_uint2(pack_h2(s.x, s.y), pack_h2(s.z, s.w));
    } else {
        ((float4*)out)[i] = s;
    }
}

// ------- 1) add + rmsnorm -> fp16 -------------------------------------------
__global__ __launch_bounds__(256) void addnorm_kernel(
    const float* __restrict__ hs,
    const float* __restrict__ res,
    const float* __restrict__ w,
    __half* __restrict__ out)
{
    int row = blockIdx.x;
    int tid = threadIdx.x;
    const float4* a4 = (const float4*)(hs  + (size_t)row * DMODEL);
    const float4* b4 = (const float4*)(res + (size_t)row * DMODEL);
    const float4* w4 = (const float4*)w;
    float4 v = a4[tid];
    float4 b = b4[tid];
    v.x += b.x; v.y += b.y; v.z += b.z; v.w += b.w;
    float ss = v.x*v.x + v.y*v.y + v.z*v.z + v.w*v.w;

    __shared__ float red[8];
    #pragma unroll
    for (int off = 16; off > 0; off >>= 1)
        ss += __shfl_xor_sync(0xffffffffu, ss, off);
    if ((tid & 31) == 0) red[tid >> 5] = ss;
    __syncthreads();
    if (tid < 32) {
        float s = (tid < 8) ? red[tid] : 0.0f;
        #pragma unroll
        for (int off = 4; off > 0; off >>= 1)
            s += __shfl_xor_sync(0xffffffffu, s, off);
        if (tid == 0) red[0] = s;
    }
    __syncthreads();
    float rstd = rsqrtf(red[0] * (1.0f / DMODEL) + 1e-5f);

    float4 ww = w4[tid];
    *(uint2*)&out[(size_t)row * DMODEL + tid * 4] =
        make_uint2(pack_h2(v.x * rstd * ww.x, v.y * rstd * ww.y),
                   pack_h2(v.z * rstd * ww.z, v.w * rstd * ww.w));
}

// ------- 3) causal depthwise conv + bias + SiLU, register-blocked ----------
// xz is fp16 now. Each thread: 4 timesteps x 4 channels.
__global__ __launch_bounds__(256) void conv_silu_kernel(
    const __half* __restrict__ xz,
    const float* __restrict__ cw,
    const float* __restrict__ cb,
    float* __restrict__ xc,
    __half* __restrict__ xch)
{
    int idx = blockIdx.x * blockDim.x + threadIdx.x;   // over (NTOK/4)*(DINNER/4)
    int dq = idx & (DINNER / 4 - 1);
    int tq = idx / (DINNER / 4);
    int d  = dq * 4;
    int t0 = tq * 4;
    int l0 = t0 & (LSEQ - 1);          // 4-aligned; only l0==0 touches pad

    float4 bias4 = *(const float4*)&cb[d];
    float4 w0 = *(const float4*)&cw[(d + 0) * 4];
    float4 w1 = *(const float4*)&cw[(d + 1) * 4];
    float4 w2 = *(const float4*)&cw[(d + 2) * 4];
    float4 w3 = *(const float4*)&cw[(d + 3) * 4];
    float wv0[4] = {w0.x, w0.y, w0.z, w0.w};
    float wv1[4] = {w1.x, w1.y, w1.z, w1.w};
    float wv2[4] = {w2.x, w2.y, w2.z, w2.w};
    float wv3[4] = {w3.x, w3.y, w3.z, w3.w};

    // rows t0-3 .. t0+3 -> v[0..6]
    float4 v[7];
    #pragma unroll
    for (int k = 0; k < 7; k++) {
        if (l0 == 0 && k < 3) {
            v[k] = make_float4(0.f, 0.f, 0.f, 0.f);
        } else {
            uint2 u = *(const uint2*)&xz[(size_t)(t0 - 3 + k) * (2 * DINNER) + d];
            float2 lo = unpack_h2(u.x);
            float2 hi = unpack_h2(u.y);
            v[k] = make_float4(lo.x, lo.y, hi.x, hi.y);
        }
    }

    #pragma unroll
    for (int r = 0; r < 4; r++) {
        float a0 = bias4.x, a1 = bias4.y, a2 = bias4.z, a3 = bias4.w;
        #pragma unroll
        for (int j = 0; j < 4; j++) {
            float4 u = v[r + j];
            a0 = fmaf(u.x, wv0[j], a0);
            a1 = fmaf(u.y, wv1[j], a1);
            a2 = fmaf(u.z, wv2[j], a2);
            a3 = fmaf(u.w, wv3[j], a3);
        }
        float4 o;
        o.x = siluf(a0); o.y = siluf(a1); o.z = siluf(a2); o.w = siluf(a3);
        size_t t = (size_t)(t0 + r);
        *(float4*)&xc[t * DINNER + d] = o;
        *(uint2*)&xch[t * DINNER + d] =
            make_uint2(pack_h2(o.x, o.y), pack_h2(o.z, o.w));
    }
}

// ------- 4) selective scan -> y fp16 (z read from fp16 xz) ------------------
__global__ __launch_bounds__(256) void scan_kernel(
    const float* __restrict__ dt,
    const __half* __restrict__ xz,
    const float* __restrict__ xc,
    const float* __restrict__ xdbl,
    const float* __restrict__ A_log,
    const float* __restrict__ Dp,
    __half* __restrict__ y)
{
    const int CH = 64;
    __shared__ float sdt[CH][16], sx[CH][16], sz[CH][16];
    __shared__ float sB[CH][16], sC[CH][16], sy[CH][16];

    int b  = blockIdx.x >> 7;
    int d0 = (blockIdx.x & 127) * 16;
    int tid = threadIdx.x;
    int c = tid >> 4;
    int n = tid & 15;
    int d = d0 + c;

    float Acoef = -expf(A_log[d * DSTATE + n]);
    float h = 0.0f;

    int e  = tid * 4;
    int le = e >> 4;
    int ie = e & 15;

    for (int l0 = 0; l0 < LSEQ; l0 += CH) {
        {
            size_t t = (size_t)b * LSEQ + l0 + le;
            *(float4*)&sdt[le][ie] = *(const float4*)&dt[t * DINNER + d0 + ie];
            *(float4*)&sx [le][ie] = *(const float4*)&xc[t * DINNER + d0 + ie];
            uint2 uz = *(const uint2*)&xz[t * (2 * DINNER) + DINNER + d0 + ie];
            float2 zlo = unpack_h2(uz.x);
            float2 zhi = unpack_h2(uz.y);
            *(float4*)&sz [le][ie] = make_float4(zlo.x, zlo.y, zhi.x, zhi.y);
            *(float4*)&sB [le][ie] = *(const float4*)&xdbl[t * NDBL + DTRANK + ie];
            *(float4*)&sC [le][ie] = *(const float4*)&xdbl[t * NDBL + DTRANK + DSTATE + ie];
        }
        __syncthreads();

        #pragma unroll 4
        for (int ll = 0; ll < CH; ll++) {
            float dtv = sdt[ll][c];
            float xv  = sx[ll][c];
            float ea  = __expf(dtv * Acoef);
            h = fmaf(ea, h, dtv * xv * sB[ll][n]);
            float p = h * sC[ll][n];
            p += __shfl_xor_sync(0xffffffffu, p, 8);
            p += __shfl_xor_sync(0xffffffffu, p, 4);
            p += __shfl_xor_sync(0xffffffffu, p, 2);
            p += __shfl_xor_sync(0xffffffffu, p, 1);
            if (n == 0) sy[ll][c] = p;
        }
        __syncthreads();

        {
            size_t t = (size_t)b * LSEQ + l0 + le;
            float4 ys = *(float4*)&sy[le][ie];
            float4 xs = *(float4*)&sx[le][ie];
            float4 zs = *(float4*)&sz[le][ie];
            float4 dd = *(const float4*)&Dp[d0 + ie];
            float o0 = (ys.x + xs.x * dd.x) * siluf(zs.x);
            float o1 = (ys.y + xs.y * dd.y) * siluf(zs.y);
            float o2 = (ys.z + xs.z * dd.z) * siluf(zs.z);
            float o3 = (ys.w + xs.w * dd.w) * siluf(zs.w);
            *(uint2*)&y[t * DINNER + d0 + ie] =
                make_uint2(pack_h2(o0, o1), pack_h2(o2, o3));
        }
        __syncthreads();
    }
}

// ---------------- launcher ----------------
extern "C" void kernel_launch(void* const* d_in, const int* in_sizes, int n_in,
                              void* d_out, int out_size)
{
    (void)in_sizes; (void)n_in; (void)out_size;
    const float* hs        = (const float*)d_in[1];
    const float* residual  = (const float*)d_in[2];
    const float* norm_w    = (const float*)d_in[3];
    const float* in_proj_w = (const float*)d_in[4];
    const float* conv_w    = (const float*)d_in[5];
    const float* conv_b    = (const float*)d_in[6];
    const float* x_proj_w  = (const float*)d_in[7];
    const float* dt_proj_w = (const float*)d_in[8];
    const float* dt_proj_b = (const float*)d_in[9];
    const float* A_log     = (const float*)d_in[10];
    const float* D_param   = (const float*)d_in[11];
    const float* out_proj_w= (const float*)d_in[12];
    float* out = (float*)d_out;

    static float* scratch = nullptr;
    if (!scratch) {
        void* p = nullptr;
        cudaGetSymbolAddress(&p, g_scratch);
        scratch = (float*)p;
        cudaFuncSetAttribute(mm_f16<0, false>, cudaFuncAttributeMaxDynamicSharedMemorySize, MM_SMEM_BYTES);
        cudaFuncSetAttribute(mm_f16<0, true>,  cudaFuncAttributeMaxDynamicSharedMemorySize, MM_SMEM_BYTES);
        cudaFuncSetAttribute(mm_f16<1, false>, cudaFuncAttributeMaxDynamicSharedMemorySize, MM_SMEM_BYTES);
    }
    float*  g_xc   = scratch + OFF_XC;
    float*  g_xdbl = scratch + OFF_XDBL;
    float*  g_dt   = scratch + OFF_DT;
    float*  g_xp   = scratch + OFF_XP;
    __half* g_xzh  = (__half*)(scratch + OFF_XZH);
    __half* g_h2   = (__half*)(scratch + OFF_H2);
    __half* g_xch  = (__half*)(scratch + OFF_XCH);
    __half* g_dtl  = (__half*)(scratch + OFF_DTL);
    __half* g_y2   = (__half*)(scratch + OFF_Y2);
    __half* g_win  = (__half*)(scratch + OFF_WIN2);
    __half* g_wxp  = (__half*)(scratch + OFF_WXP2);
    __half* g_wdt  = (__half*)(scratch + OFF_WDT2);
    __half* g_wop  = (__half*)(scratch + OFF_WOP2);

    // 0) all weights fp32 -> fp16 in one launch
    w2h_all_kernel<<<(S_ALL + 255) / 256, 256>>>(
        (const float4*)in_proj_w, (const float4*)x_proj_w,
        (const float4*)dt_proj_w, (const float4*)out_proj_w,
        (uint2*)g_win, (uint2*)g_wxp, (uint2*)g_wdt, (uint2*)g_wop);

    // 1) h = fp16(rmsnorm(hidden + residual) * w)
    addnorm_kernel<<<NTOK, 256>>>(hs, residual, norm_w, g_h2);

    // 2) xz = h @ in_proj_w^T   [4096 x 4096], K=1024, fp16 OUTPUT
    mm_f16<0, true><<<dim3(4096 / 128, NTOK / 128, 1), 256, MM_SMEM_BYTES>>>(
        g_h2, DMODEL, g_win, 2 * DINNER, nullptr,
        g_xzh, 2 * DINNER, 2 * DINNER, DMODEL, 0);

    // 3) xc = silu(causal_conv(x) + b)  -> fp32 (scan) + fp16 (x_proj)
    conv_silu_kernel<<<(NTOK / 4) * (DINNER / 4) / 256, 256>>>(
        g_xzh, conv_w, conv_b, g_xc, g_xch);

    // 4) x_dbl partials = xc @ x_proj_w^T   [4096 x 96], K=2048, split-K=8
    mm_f16<0, false><<<dim3(1, NTOK / 128, XP_SPLITS), 256, MM_SMEM_BYTES>>>(
        g_xch, DINNER, g_wxp, NDBL, nullptr,
        g_xp, NDBL, NDBL, DINNER / XP_SPLITS, (size_t)NTOK * NDBL);
    reduce_splits_kernel<<<(NTOK * NDBL / 4 + 255) / 256, 256>>>(
        g_xp, g_xdbl, g_dtl, NTOK * NDBL / 4);

    // 5) dt = softplus(dtlow @ dt_proj_w^T + b)   [4096 x 2048], K=64
    mm_f16<1, false><<<dim3(DINNER / 128, NTOK / 128, 1), 256, MM_SMEM_BYTES>>>(
        g_dtl, DTRANK, g_wdt, DINNER, dt_proj_b,
        g_dt, DINNER, DINNER, DTRANK, 0);

    // 6) selective scan + gate -> y (fp16 for out_proj)
    scan_kernel<<<BATCH * (DINNER / 16), 256>>>(
        g_dt, g_xzh, g_xc, g_xdbl, A_log, D_param, g_y2);

    // 7) out = y @ out_proj_w^T   [4096 x 1024], K=2048
    mm_f16<0, false><<<dim3(DMODEL / 128, NTOK / 128, 1), 256, MM_SMEM_BYTES>>>(
        g_y2, DINNER, g_wop, DMODEL, nullptr,
        out, DMODEL, DMODEL, DINNER, 0);
}

// round 13
// speedup vs baseline: 2.3025x; 1.0102x over previous
#include <cuda_runtime.h>
#include <cuda_fp16.h>
#include <cstdint>

// ---------------- Problem constants ----------------
#define BATCH   2
#define LSEQ    2048
#define NTOK    (BATCH * LSEQ)      // 4096 tokens
#define DMODEL  1024
#define DINNER  2048
#define DSTATE  16
#define DCONV   4
#define DTRANK  64
#define NDBL    (DTRANK + 2 * DSTATE)   // 96
#define XP_SPLITS 8

// ---------------- Scratch (device globals; no allocation allowed) ----------
// fp32 regions (sizes in floats)
#define OFF_XDBL  ((size_t)0)                                   // NTOK*96
#define OFF_XP    (OFF_XDBL + (size_t)NTOK * NDBL)              // 8*NTOK*96
// half regions (sizes in floats = halfs/2)
#define OFF_XZH   (OFF_XP   + (size_t)XP_SPLITS * NTOK * NDBL)  // NTOK*4096/2
#define OFF_H2    (OFF_XZH  + (size_t)NTOK * 2 * DINNER / 2)
#define OFF_XCH   (OFF_H2   + (size_t)NTOK * DMODEL / 2)
#define OFF_DTL   (OFF_XCH  + (size_t)NTOK * DINNER / 2)
#define OFF_DTH   (OFF_DTL  + (size_t)NTOK * DTRANK / 2)        // NTOK*2048/2
#define OFF_Y2    (OFF_DTH  + (size_t)NTOK * DINNER / 2)
#define OFF_WIN2  (OFF_Y2   + (size_t)NTOK * DINNER / 2)
#define OFF_WXP2  (OFF_WIN2 + (size_t)2 * DINNER * DMODEL / 2)
#define OFF_WDT2  (OFF_WXP2 + (size_t)NDBL * DINNER / 2)
#define OFF_WOP2  (OFF_WDT2 + (size_t)DINNER * DTRANK / 2)
#define SCRATCH_FLOATS (OFF_WOP2 + (size_t)DMODEL * DINNER / 2)

__device__ float g_scratch[SCRATCH_FLOATS];

// ---------------- helpers ----------------
__device__ __forceinline__ float siluf(float z) {
    return z * (1.0f / (1.0f + __expf(-z)));
}
__device__ __forceinline__ float softplusf(float v) {
    return fmaxf(v, 0.0f) + log1pf(expf(-fabsf(v)));
}

__device__ __forceinline__ uint32_t smem_u32(const void* p) {
    uint32_t addr;
    asm("{ .reg .u64 tmp; cvta.to.shared.u64 tmp, %1; cvt.u32.u64 %0, tmp; }"
        : "=r"(addr) : "l"(p));
    return addr;
}

__device__ __forceinline__ void cp16(uint32_t dst, const void* src) {
    asm volatile("cp.async.cg.shared.global [%0], [%1], 16;" :: "r"(dst), "l"(src));
}
__device__ __forceinline__ void cp_commit() {
    asm volatile("cp.async.commit_group;");
}
template <int N>
__device__ __forceinline__ void cp_wait() {
    asm volatile("cp.async.wait_group %0;" :: "n"(N));
}

__device__ __forceinline__ void ldsm_x4(
    uint32_t& r0, uint32_t& r1, uint32_t& r2, uint32_t& r3, uint32_t addr)
{
    asm volatile(
        "ldmatrix.sync.aligned.m8n8.x4.shared.b16 {%0,%1,%2,%3}, [%4];"
        : "=r"(r0), "=r"(r1), "=r"(r2), "=r"(r3) : "r"(addr));
}

// D(16x8) += A(16x16) * B(16x8), f16 inputs, f32 accumulate
__device__ __forceinline__ void mma_f16(
    float& c0, float& c1, float& c2, float& c3,
    uint32_t a0, uint32_t a1, uint32_t a2, uint32_t a3,
    uint32_t b0, uint32_t b1)
{
    asm volatile(
        "mma.sync.aligned.m16n8k16.row.col.f32.f16.f16.f32 "
        "{%0,%1,%2,%3}, {%4,%5,%6,%7}, {%8,%9}, {%0,%1,%2,%3};"
        : "+f"(c0), "+f"(c1), "+f"(c2), "+f"(c3)
        : "r"(a0), "r"(a1), "r"(a2), "r"(a3), "r"(b0), "r"(b1));
}

__device__ __forceinline__ uint32_t pack_h2(float a, float b) {
    __half2 h = __floats2half2_rn(a, b);
    return *(uint32_t*)&h;
}
__device__ __forceinline__ float2 unpack_h2(uint32_t u) {
    __half2 h = *(__half2*)&u;
    return __half22float2(h);
}

// ------------- all weights fp32 -> fp16 in ONE launch -----------------------
#define S_IN  ((int)(2 * DINNER * DMODEL / 4))   // 1,048,576 float4s
#define S_XP  ((int)(NDBL * DINNER / 4))         //    49,152
#define S_DT  ((int)(DINNER * DTRANK / 4))       //    32,768
#define S_OP  ((int)(DMODEL * DINNER / 4))       //   524,288
#define S_ALL (S_IN + S_XP + S_DT + S_OP)

__global__ __launch_bounds__(256) void w2h_all_kernel(
    const float4* __restrict__ win, const float4* __restrict__ wxp,
    const float4* __restrict__ wdt, const float4* __restrict__ wop,
    uint2* __restrict__ owin, uint2* __restrict__ owxp,
    uint2* __restrict__ owdt, uint2* __restrict__ owop)
{
    int i = blockIdx.x * blockDim.x + threadIdx.x;
    if (i >= S_ALL) return;
    const float4* src; uint2* dst; int j;
    if (i < S_IN)                    { src = win; dst = owin; j = i; }
    else if (i < S_IN + S_XP)        { src = wxp; dst = owxp; j = i - S_IN; }
    else if (i < S_IN + S_XP + S_DT) { src = wdt; dst = owdt; j = i - S_IN - S_XP; }
    else                             { src = wop; dst = owop; j = i - S_IN - S_XP - S_DT; }
    float4 v = src[j];
    dst[j] = make_uint2(pack_h2(v.x, v.y), pack_h2(v.z, v.w));
}

// ---------------- FP16 tensor-core GEMM: C[m,n] = sum_k A[m,k] * W[n,k] ----
// CTA: 128x128x64, 256 threads, 8 warps (2 M x 4 N), warp 64x32.
// 3-stage cp.async pipeline, one __syncthreads per 64-k iter, ldmatrix frags.
// EPI: 0 = plain store, 1 = softplus(c + bias[n]).
// HOUT: store __half output instead of fp32.
#define ROWB 144                            // bytes per smem row (128 data + 16 pad)
#define TILE_B (128 * ROWB)                 // 18432
#define STAGE_B (2 * TILE_B)                // A + B
#define MM_SMEM_BYTES (3 * STAGE_B)         // 110592

__device__ __forceinline__ void stage_tile(
    uint32_t sA, uint32_t sB,
    const __half* __restrict__ A, int lda,
    const __half* __restrict__ W, int ldw, int Nw,
    int m0, int n0, int k0, int tid)
{
    #pragma unroll
    for (int i = 0; i < 4; i++) {
        int idx = i * 256 + tid;            // 0..1023
        int row = idx >> 3;
        int c   = idx & 7;                  // 16B chunk (8 halfs)
        cp16(sA + (uint32_t)(row * ROWB + c * 16),
             &A[(size_t)(m0 + row) * lda + k0 + c * 8]);
    }
    #pragma unroll
    for (int i = 0; i < 4; i++) {
        int idx = i * 256 + tid;
        int row = idx >> 3;
        int c   = idx & 7;
        int n = n0 + row;
        int nn = (n < Nw) ? n : 0;          // clamp; garbage cols never stored
        cp16(sB + (uint32_t)(row * ROWB + c * 16),
             &W[(size_t)nn * ldw + k0 + c * 8]);
    }
}

template <int EPI, bool HOUT>
__global__ __launch_bounds__(256, 2) void mm_f16(
    const __half* __restrict__ A, int lda,
    const __half* __restrict__ W, int Nw,     // valid W rows
    const float* __restrict__ bias,
    void* __restrict__ Cv, int ldc, int Nc,   // valid C cols
    int K,                                     // K per z-slice (multiple of 64)
    size_t cSlice)                             // C offset per z-slice (elements)
{
    extern __shared__ char smem_c[];
    const uint32_t sbase = smem_u32(smem_c);
    const int tid  = threadIdx.x;
    const int wid  = tid >> 5;
    const int lane = tid & 31;
    const int g    = lane >> 2;
    const int t4   = lane & 3;
    const int wm   = wid >> 2;                // 0..1
    const int wn   = wid & 3;                 // 0..3
    const int mW   = wm * 64;
    const int nW   = wn * 32;
    const int m0 = blockIdx.y * 128;
    const int n0 = blockIdx.x * 128;
    const int kBase = blockIdx.z * K;
    const int iters = K / 64;

    const size_t zoff = (size_t)blockIdx.z * cSlice;
    const int ldw = K * gridDim.z;

    const uint32_t offA = (uint32_t)((mW + (lane & 15)) * ROWB + (lane >> 4) * 16);
    const uint32_t offB = (uint32_t)((nW + (lane & 15)) * ROWB + (lane >> 4) * 16);

    float acc[4][4][4];
    #pragma unroll
    for (int i = 0; i < 4; i++)
        #pragma unroll
        for (int j = 0; j < 4; j++)
            #pragma unroll
            for (int q = 0; q < 4; q++) acc[i][j][q] = 0.0f;

    // prologue: stage tiles 0 and 1 (clamped when iters == 1)
    stage_tile(sbase, sbase + TILE_B, A, lda, W, ldw, Nw, m0, n0, kBase, tid);
    cp_commit();
    {
        int k1 = (iters > 1) ? kBase + 64 : kBase;
        stage_tile(sbase + STAGE_B, sbase + STAGE_B + TILE_B,
                   A, lda, W, ldw, Nw, m0, n0, k1, tid);
    }
    cp_commit();

    for (int it = 0; it < iters; it++) {
        cp_wait<1>();
        __syncthreads();

        if (it + 2 < iters) {
            int s = (it + 2) % 3;
            stage_tile(sbase + (uint32_t)s * STAGE_B,
                       sbase + (uint32_t)s * STAGE_B + TILE_B,
                       A, lda, W, ldw, Nw, m0, n0, kBase + (it + 2) * 64, tid);
        }
        cp_commit();

        const uint32_t aBase = sbase + (uint32_t)(it % 3) * STAGE_B;
        const uint32_t bBase = aBase + TILE_B;

        #pragma unroll
        for (int ks = 0; ks < 4; ks++) {       // four k16 steps per 64-k tile
            uint32_t b0r[4], b1r[4];
            ldsm_x4(b0r[0], b0r[1], b0r[2], b0r[3], bBase + offB + ks * 32);
            ldsm_x4(b1r[0], b1r[1], b1r[2], b1r[3],
                    bBase + offB + 16 * ROWB + ks * 32);
            #pragma unroll
            for (int i = 0; i < 4; i++) {
                uint32_t a0, a1, a2, a3;
                ldsm_x4(a0, a1, a2, a3,
                        aBase + offA + (uint32_t)(i * 16 * ROWB) + ks * 32);
                mma_f16(acc[i][0][0], acc[i][0][1], acc[i][0][2], acc[i][0][3],
                        a0, a1, a2, a3, b0r[0], b0r[2]);
                mma_f16(acc[i][1][0], acc[i][1][1], acc[i][1][2], acc[i][1][3],
                        a0, a1, a2, a3, b0r[1], b0r[3]);
                mma_f16(acc[i][2][0], acc[i][2][1], acc[i][2][2], acc[i][2][3],
                        a0, a1, a2, a3, b1r[0], b1r[2]);
                mma_f16(acc[i][3][0], acc[i][3][1], acc[i][3][2], acc[i][3][3],
                        a0, a1, a2, a3, b1r[1], b1r[3]);
            }
        }
    }

    // ---- epilogue: registers -> global ----
    #pragma unroll
    for (int i = 0; i < 4; i++) {
        #pragma unroll
        for (int j = 0; j < 4; j++) {
            int col = n0 + nW + j * 8 + t4 * 2;
            if (col < Nc) {
                int row0 = m0 + mW + i * 16 + g;
                float2 v0 = make_float2(acc[i][j][0], acc[i][j][1]);
                float2 v1 = make_float2(acc[i][j][2], acc[i][j][3]);
                if (EPI == 1) {
                    v0.x = softplusf(v0.x + bias[col]);
                    v0.y = softplusf(v0.y + bias[col + 1]);
                    v1.x = softplusf(v1.x + bias[col]);
                    v1.y = softplusf(v1.y + bias[col + 1]);
                }
                if (HOUT) {
                    __half* Ch = (__half*)Cv + zoff;
                    *(uint32_t*)&Ch[(size_t)row0 * ldc + col] = pack_h2(v0.x, v0.y);
                    *(uint32_t*)&Ch[(size_t)(row0 + 8) * ldc + col] = pack_h2(v1.x, v1.y);
                } else {
                    float* Cf = (float*)Cv + zoff;
                    *(float2*)&Cf[(size_t)row0 * ldc + col]       = v0;
                    *(float2*)&Cf[(size_t)(row0 + 8) * ldc + col] = v1;
                }
            }
        }
    }
}

// ---------------- split-K partial reduce ------------------------------------
__global__ __launch_bounds__(256) void reduce_splits_kernel(
    const float* __restrict__ part, float* __restrict__ out,
    __half* __restrict__ dtlow, int n4)
{
    int i = blockIdx.x * blockDim.x + threadIdx.x;
    if (i >= n4) return;
    const float4* p = (const float4*)part;
    float4 s = p[i];
    #pragma unroll
    for (int k = 1; k < XP_SPLITS; k++) {
        float4 v = p[(size_t)k * n4 + i];
        s.x += v.x; s.y += v.y; s.z += v.z; s.w += v.w;
    }
    int cq = i % (NDBL / 4);
    if (cq < (DTRANK / 4)) {
        int row = i / (NDBL / 4);
        *(uint2*)&dtlow[(size_t)row * DTRANK + cq * 4] =
            make_uint2(pack_h2(s.x, s.y), pack_h2(s.z, s.w));
    } else {
        ((float4*)out)[i] = s;
    }
}

// ------- 1) add + rmsnorm -> fp16 -------------------------------------------
__global__ __launch_bounds__(256) void addnorm_kernel(
    const float* __restrict__ hs,
    const float* __restrict__ res,
    const float* __restrict__ w,
    __half* __restrict__ out)
{
    int row = blockIdx.x;
    int tid = threadIdx.x;
    const float4* a4 = (const float4*)(hs  + (size_t)row * DMODEL);
    const float4* b4 = (const float4*)(res + (size_t)row * DMODEL);
    const float4* w4 = (const float4*)w;
    float4 v = a4[tid];
    float4 b = b4[tid];
    v.x += b.x; v.y += b.y; v.z += b.z; v.w += b.w;
    float ss = v.x*v.x + v.y*v.y + v.z*v.z + v.w*v.w;

    __shared__ float red[8];
    #pragma unroll
    for (int off = 16; off > 0; off >>= 1)
        ss += __shfl_xor_sync(0xffffffffu, ss, off);
    if ((tid & 31) == 0) red[tid >> 5] = ss;
    __syncthreads();
    if (tid < 32) {
        float s = (tid < 8) ? red[tid] : 0.0f;
        #pragma unroll
        for (int off = 4; off > 0; off >>= 1)
            s += __shfl_xor_sync(0xffffffffu, s, off);
        if (tid == 0) red[0] = s;
    }
    __syncthreads();
    float rstd = rsqrtf(red[0] * (1.0f / DMODEL) + 1e-5f);

    float4 ww = w4[tid];
    *(uint2*)&out[(size_t)row * DMODEL + tid * 4] =
        make_uint2(pack_h2(v.x * rstd * ww.x, v.y * rstd * ww.y),
                   pack_h2(v.z * rstd * ww.z, v.w * rstd * ww.w));
}

// ------- 3) causal depthwise conv + bias + SiLU -> fp16 only ----------------
__global__ __launch_bounds__(256) void conv_silu_kernel(
    const __half* __restrict__ xz,
    const float* __restrict__ cw,
    const float* __restrict__ cb,
    __half* __restrict__ xch)
{
    int idx = blockIdx.x * blockDim.x + threadIdx.x;   // over (NTOK/4)*(DINNER/4)
    int dq = idx & (DINNER / 4 - 1);
    int tq = idx / (DINNER / 4);
    int d  = dq * 4;
    int t0 = tq * 4;
    int l0 = t0 & (LSEQ - 1);          // 4-aligned; only l0==0 touches pad

    float4 bias4 = *(const float4*)&cb[d];
    float4 w0 = *(const float4*)&cw[(d + 0) * 4];
    float4 w1 = *(const float4*)&cw[(d + 1) * 4];
    float4 w2 = *(const float4*)&cw[(d + 2) * 4];
    float4 w3 = *(const float4*)&cw[(d + 3) * 4];
    float wv0[4] = {w0.x, w0.y, w0.z, w0.w};
    float wv1[4] = {w1.x, w1.y, w1.z, w1.w};
    float wv2[4] = {w2.x, w2.y, w2.z, w2.w};
    float wv3[4] = {w3.x, w3.y, w3.z, w3.w};

    // rows t0-3 .. t0+3 -> v[0..6]
    float4 v[7];
    #pragma unroll
    for (int k = 0; k < 7; k++) {
        if (l0 == 0 && k < 3) {
            v[k] = make_float4(0.f, 0.f, 0.f, 0.f);
        } else {
            uint2 u = *(const uint2*)&xz[(size_t)(t0 - 3 + k) * (2 * DINNER) + d];
            float2 lo = unpack_h2(u.x);
            float2 hi = unpack_h2(u.y);
            v[k] = make_float4(lo.x, lo.y, hi.x, hi.y);
        }
    }

    #pragma unroll
    for (int r = 0; r < 4; r++) {
        float a0 = bias4.x, a1 = bias4.y, a2 = bias4.z, a3 = bias4.w;
        #pragma unroll
        for (int j = 0; j < 4; j++) {
            float4 u = v[r + j];
            a0 = fmaf(u.x, wv0[j], a0);
            a1 = fmaf(u.y, wv1[j], a1);
            a2 = fmaf(u.z, wv2[j], a2);
            a3 = fmaf(u.w, wv3[j], a3);
        }
        size_t t = (size_t)(t0 + r);
        *(uint2*)&xch[t * DINNER + d] =
            make_uint2(pack_h2(siluf(a0), siluf(a1)),
                       pack_h2(siluf(a2), siluf(a3)));
    }
}

// ------- 4) selective scan (dt/x/z fp16 inputs) -> y fp16 -------------------
__global__ __launch_bounds__(256) void scan_kernel(
    const __half* __restrict__ dt,
    const __half* __restrict__ xz,
    const __half* __restrict__ xch,
    const float* __restrict__ xdbl,
    const float* __restrict__ A_log,
    const float* __restrict__ Dp,
    __half* __restrict__ y)
{
    const int CH = 64;
    __shared__ float sdt[CH][16], sx[CH][16], sz[CH][16];
    __shared__ float sB[CH][16], sC[CH][16], sy[CH][16];

    int b  = blockIdx.x >> 7;
    int d0 = (blockIdx.x & 127) * 16;
    int tid = threadIdx.x;
    int c = tid >> 4;
    int n = tid & 15;
    int d = d0 + c;

    float Acoef = -expf(A_log[d * DSTATE + n]);
    float h = 0.0f;

    int e  = tid * 4;
    int le = e >> 4;
    int ie = e & 15;

    for (int l0 = 0; l0 < LSEQ; l0 += CH) {
        {
            size_t t = (size_t)b * LSEQ + l0 + le;
            uint2 ud = *(const uint2*)&dt[t * DINNER + d0 + ie];
            float2 dlo = unpack_h2(ud.x), dhi = unpack_h2(ud.y);
            *(float4*)&sdt[le][ie] = make_float4(dlo.x, dlo.y, dhi.x, dhi.y);
            uint2 ux = *(const uint2*)&xch[t * DINNER + d0 + ie];
            float2 xlo = unpack_h2(ux.x), xhi = unpack_h2(ux.y);
            *(float4*)&sx [le][ie] = make_float4(xlo.x, xlo.y, xhi.x, xhi.y);
            uint2 uz = *(const uint2*)&xz[t * (2 * DINNER) + DINNER + d0 + ie];
            float2 zlo = unpack_h2(uz.x), zhi = unpack_h2(uz.y);
            *(float4*)&sz [le][ie] = make_float4(zlo.x, zlo.y, zhi.x, zhi.y);
            *(float4*)&sB [le][ie] = *(const float4*)&xdbl[t * NDBL + DTRANK + ie];
            *(float4*)&sC [le][ie] = *(const float4*)&xdbl[t * NDBL + DTRANK + DSTATE + ie];
        }
        __syncthreads();

        #pragma unroll 4
        for (int ll = 0; ll < CH; ll++) {
            float dtv = sdt[ll][c];
            float xv  = sx[ll][c];
            float ea  = __expf(dtv * Acoef);
            h = fmaf(ea, h, dtv * xv * sB[ll][n]);
            float p = h * sC[ll][n];
            p += __shfl_xor_sync(0xffffffffu, p, 8);
            p += __shfl_xor_sync(0xffffffffu, p, 4);
            p += __shfl_xor_sync(0xffffffffu, p, 2);
            p += __shfl_xor_sync(0xffffffffu, p, 1);
            if (n == 0) sy[ll][c] = p;
        }
        __syncthreads();

        {
            size_t t = (size_t)b * LSEQ + l0 + le;
            float4 ys = *(float4*)&sy[le][ie];
            float4 xs = *(float4*)&sx[le][ie];
            float4 zs = *(float4*)&sz[le][ie];
            float4 dd = *(const float4*)&Dp[d0 + ie];
            float o0 = (ys.x + xs.x * dd.x) * siluf(zs.x);
            float o1 = (ys.y + xs.y * dd.y) * siluf(zs.y);
            float o2 = (ys.z + xs.z * dd.z) * siluf(zs.z);
            float o3 = (ys.w + xs.w * dd.w) * siluf(zs.w);
            *(uint2*)&y[t * DINNER + d0 + ie] =
                make_uint2(pack_h2(o0, o1), pack_h2(o2, o3));
        }
        __syncthreads();
    }
}

// ---------------- launcher ----------------
extern "C" void kernel_launch(void* const* d_in, const int* in_sizes, int n_in,
                              void* d_out, int out_size)
{
    (void)in_sizes; (void)n_in; (void)out_size;
    const float* hs        = (const float*)d_in[1];
    const float* residual  = (const float*)d_in[2];
    const float* norm_w    = (const float*)d_in[3];
    const float* in_proj_w = (const float*)d_in[4];
    const float* conv_w    = (const float*)d_in[5];
    const float* conv_b    = (const float*)d_in[6];
    const float* x_proj_w  = (const float*)d_in[7];
    const float* dt_proj_w = (const float*)d_in[8];
    const float* dt_proj_b = (const float*)d_in[9];
    const float* A_log     = (const float*)d_in[10];
    const float* D_param   = (const float*)d_in[11];
    const float* out_proj_w= (const float*)d_in[12];
    float* out = (float*)d_out;

    static float* scratch = nullptr;
    if (!scratch) {
        void* p = nullptr;
        cudaGetSymbolAddress(&p, g_scratch);
        scratch = (float*)p;
        cudaFuncSetAttribute(mm_f16<0, false>, cudaFuncAttributeMaxDynamicSharedMemorySize, MM_SMEM_BYTES);
        cudaFuncSetAttribute(mm_f16<0, true>,  cudaFuncAttributeMaxDynamicSharedMemorySize, MM_SMEM_BYTES);
        cudaFuncSetAttribute(mm_f16<1, true>,  cudaFuncAttributeMaxDynamicSharedMemorySize, MM_SMEM_BYTES);
    }
    float*  g_xdbl = scratch + OFF_XDBL;
    float*  g_xp   = scratch + OFF_XP;
    __half* g_xzh  = (__half*)(scratch + OFF_XZH);
    __half* g_h2   = (__half*)(scratch + OFF_H2);
    __half* g_xch  = (__half*)(scratch + OFF_XCH);
    __half* g_dtl  = (__half*)(scratch + OFF_DTL);
    __half* g_dth  = (__half*)(scratch + OFF_DTH);
    __half* g_y2   = (__half*)(scratch + OFF_Y2);
    __half* g_win  = (__half*)(scratch + OFF_WIN2);
    __half* g_wxp  = (__half*)(scratch + OFF_WXP2);
    __half* g_wdt  = (__half*)(scratch + OFF_WDT2);
    __half* g_wop  = (__half*)(scratch + OFF_WOP2);

    // 0) all weights fp32 -> fp16 in one launch
    w2h_all_kernel<<<(S_ALL + 255) / 256, 256>>>(
        (const float4*)in_proj_w, (const float4*)x_proj_w,
        (const float4*)dt_proj_w, (const float4*)out_proj_w,
        (uint2*)g_win, (uint2*)g_wxp, (uint2*)g_wdt, (uint2*)g_wop);

    // 1) h = fp16(rmsnorm(hidden + residual) * w)
    addnorm_kernel<<<NTOK, 256>>>(hs, residual, norm_w, g_h2);

    // 2) xz = h @ in_proj_w^T   [4096 x 4096], K=1024, fp16 output
    mm_f16<0, true><<<dim3(4096 / 128, NTOK / 128, 1), 256, MM_SMEM_BYTES>>>(
        g_h2, DMODEL, g_win, 2 * DINNER, nullptr,
        g_xzh, 2 * DINNER, 2 * DINNER, DMODEL, 0);

    // 3) xc = silu(causal_conv(x) + b)  -> fp16 only
    conv_silu_kernel<<<(NTOK / 4) * (DINNER / 4) / 256, 256>>>(
        g_xzh, conv_w, conv_b, g_xch);

    // 4) x_dbl partials = xc @ x_proj_w^T   [4096 x 96], K=2048, split-K=8
    mm_f16<0, false><<<dim3(1, NTOK / 128, XP_SPLITS), 256, MM_SMEM_BYTES>>>(
        g_xch, DINNER, g_wxp, NDBL, nullptr,
        g_xp, NDBL, NDBL, DINNER / XP_SPLITS, (size_t)NTOK * NDBL);
    reduce_splits_kernel<<<(NTOK * NDBL / 4 + 255) / 256, 256>>>(
        g_xp, g_xdbl, g_dtl, NTOK * NDBL / 4);

    // 5) dt = softplus(dtlow @ dt_proj_w^T + b)   [4096 x 2048], K=64, fp16 out
    mm_f16<1, true><<<dim3(DINNER / 128, NTOK / 128, 1), 256, MM_SMEM_BYTES>>>(
        g_dtl, DTRANK, g_wdt, DINNER, dt_proj_b,
        g_dth, DINNER, DINNER, DTRANK, 0);

    // 6) selective scan + gate -> y (fp16 for out_proj)
    scan_kernel<<<BATCH * (DINNER / 16), 256>>>(
        g_dth, g_xzh, g_xch, g_xdbl, A_log, D_param, g_y2);

    // 7) out = y @ out_proj_w^T   [4096 x 1024], K=2048
    mm_f16<0, false><<<dim3(DMODEL / 128, NTOK / 128, 1), 256, MM_SMEM_BYTES>>>(
        g_y2, DINNER, g_wop, DMODEL, nullptr,
        out, DMODEL, DMODEL, DINNER, 0);
}

// round 14
// speedup vs baseline: 2.4892x; 1.0810x over previous
#include <cuda_runtime.h>
#include <cuda_fp16.h>
#include <cstdint>

// ---------------- Problem constants ----------------
#define BATCH   2
#define LSEQ    2048
#define NTOK    (BATCH * LSEQ)      // 4096 tokens
#define DMODEL  1024
#define DINNER  2048
#define DSTATE  16
#define DCONV   4
#define DTRANK  64
#define NDBL    (DTRANK + 2 * DSTATE)   // 96
#define XP_SPLITS 8
#define NCHUNK  8
#define CLEN    (LSEQ / NCHUNK)     // 256

// ---------------- Scratch (device globals; no allocation allowed) ----------
// fp32 regions (sizes in floats)
#define OFF_XDBL  ((size_t)0)                                   // NTOK*96
#define OFF_XP    (OFF_XDBL + (size_t)NTOK * NDBL)              // 8*NTOK*96
#define Q_SZ      ((size_t)BATCH * 128 * NCHUNK * 256)          // 524288
#define OFF_Q     (OFF_XP   + (size_t)XP_SPLITS * NTOK * NDBL)
#define OFF_P     (OFF_Q    + Q_SZ)
#define OFF_HP    (OFF_P    + Q_SZ)
// half regions (sizes in floats = halfs/2)
#define OFF_XZH   (OFF_HP   + Q_SZ)
#define OFF_H2    (OFF_XZH  + (size_t)NTOK * 2 * DINNER / 2)
#define OFF_XCH   (OFF_H2   + (size_t)NTOK * DMODEL / 2)
#define OFF_DTL   (OFF_XCH  + (size_t)NTOK * DINNER / 2)
#define OFF_DTH   (OFF_DTL  + (size_t)NTOK * DTRANK / 2)
#define OFF_Y2    (OFF_DTH  + (size_t)NTOK * DINNER / 2)
#define OFF_WIN2  (OFF_Y2   + (size_t)NTOK * DINNER / 2)
#define OFF_WXP2  (OFF_WIN2 + (size_t)2 * DINNER * DMODEL / 2)
#define OFF_WDT2  (OFF_WXP2 + (size_t)NDBL * DINNER / 2)
#define OFF_WOP2  (OFF_WDT2 + (size_t)DINNER * DTRANK / 2)
#define SCRATCH_FLOATS (OFF_WOP2 + (size_t)DMODEL * DINNER / 2)

__device__ float g_scratch[SCRATCH_FLOATS];

// ---------------- helpers ----------------
__device__ __forceinline__ float siluf(float z) {
    return z * (1.0f / (1.0f + __expf(-z)));
}
__device__ __forceinline__ float softplusf(float v) {
    return fmaxf(v, 0.0f) + log1pf(expf(-fabsf(v)));
}

__device__ __forceinline__ uint32_t smem_u32(const void* p) {
    uint32_t addr;
    asm("{ .reg .u64 tmp; cvta.to.shared.u64 tmp, %1; cvt.u32.u64 %0, tmp; }"
        : "=r"(addr) : "l"(p));
    return addr;
}

__device__ __forceinline__ void cp16(uint32_t dst, const void* src) {
    asm volatile("cp.async.cg.shared.global [%0], [%1], 16;" :: "r"(dst), "l"(src));
}
__device__ __forceinline__ void cp_commit() {
    asm volatile("cp.async.commit_group;");
}
template <int N>
__device__ __forceinline__ void cp_wait() {
    asm volatile("cp.async.wait_group %0;" :: "n"(N));
}

__device__ __forceinline__ void ldsm_x4(
    uint32_t& r0, uint32_t& r1, uint32_t& r2, uint32_t& r3, uint32_t addr)
{
    asm volatile(
        "ldmatrix.sync.aligned.m8n8.x4.shared.b16 {%0,%1,%2,%3}, [%4];"
        : "=r"(r0), "=r"(r1), "=r"(r2), "=r"(r3) : "r"(addr));
}

// D(16x8) += A(16x16) * B(16x8), f16 inputs, f32 accumulate
__device__ __forceinline__ void mma_f16(
    float& c0, float& c1, float& c2, float& c3,
    uint32_t a0, uint32_t a1, uint32_t a2, uint32_t a3,
    uint32_t b0, uint32_t b1)
{
    asm volatile(
        "mma.sync.aligned.m16n8k16.row.col.f32.f16.f16.f32 "
        "{%0,%1,%2,%3}, {%4,%5,%6,%7}, {%8,%9}, {%0,%1,%2,%3};"
        : "+f"(c0), "+f"(c1), "+f"(c2), "+f"(c3)
        : "r"(a0), "r"(a1), "r"(a2), "r"(a3), "r"(b0), "r"(b1));
}

__device__ __forceinline__ uint32_t pack_h2(float a, float b) {
    __half2 h = __floats2half2_rn(a, b);
    return *(uint32_t*)&h;
}
__device__ __forceinline__ float2 unpack_h2(uint32_t u) {
    __half2 h = *(__half2*)&u;
    return __half22float2(h);
}

// ------------- all weights fp32 -> fp16 in ONE launch -----------------------
#define S_IN  ((int)(2 * DINNER * DMODEL / 4))   // 1,048,576 float4s
#define S_XP  ((int)(NDBL * DINNER / 4))         //    49,152
#define S_DT  ((int)(DINNER * DTRANK / 4))       //    32,768
#define S_OP  ((int)(DMODEL * DINNER / 4))       //   524,288
#define S_ALL (S_IN + S_XP + S_DT + S_OP)

__global__ __launch_bounds__(256) void w2h_all_kernel(
    const float4* __restrict__ win, const float4* __restrict__ wxp,
    const float4* __restrict__ wdt, const float4* __restrict__ wop,
    uint2* __restrict__ owin, uint2* __restrict__ owxp,
    uint2* __restrict__ owdt, uint2* __restrict__ owop)
{
    int i = blockIdx.x * blockDim.x + threadIdx.x;
    if (i >= S_ALL) return;
    const float4* src; uint2* dst; int j;
    if (i < S_IN)                    { src = win; dst = owin; j = i; }
    else if (i < S_IN + S_XP)        { src = wxp; dst = owxp; j = i - S_IN; }
    else if (i < S_IN + S_XP + S_DT) { src = wdt; dst = owdt; j = i - S_IN - S_XP; }
    else                             { src = wop; dst = owop; j = i - S_IN - S_XP - S_DT; }
    float4 v = src[j];
    dst[j] = make_uint2(pack_h2(v.x, v.y), pack_h2(v.z, v.w));
}

// ---------------- FP16 tensor-core GEMM: C[m,n] = sum_k A[m,k] * W[n,k] ----
#define ROWB 144
#define TILE_B (128 * ROWB)
#define STAGE_B (2 * TILE_B)
#define MM_SMEM_BYTES (3 * STAGE_B)         // 110592

__device__ __forceinline__ void stage_tile(
    uint32_t sA, uint32_t sB,
    const __half* __restrict__ A, int lda,
    const __half* __restrict__ W, int ldw, int Nw,
    int m0, int n0, int k0, int tid)
{
    #pragma unroll
    for (int i = 0; i < 4; i++) {
        int idx = i * 256 + tid;
        int row = idx >> 3;
        int c   = idx & 7;
        cp16(sA + (uint32_t)(row * ROWB + c * 16),
             &A[(size_t)(m0 + row) * lda + k0 + c * 8]);
    }
    #pragma unroll
    for (int i = 0; i < 4; i++) {
        int idx = i * 256 + tid;
        int row = idx >> 3;
        int c   = idx & 7;
        int n = n0 + row;
        int nn = (n < Nw) ? n : 0;
        cp16(sB + (uint32_t)(row * ROWB + c * 16),
             &W[(size_t)nn * ldw + k0 + c * 8]);
    }
}

template <int EPI, bool HOUT>
__global__ __launch_bounds__(256, 2) void mm_f16(
    const __half* __restrict__ A, int lda,
    const __half* __restrict__ W, int Nw,
    const float* __restrict__ bias,
    void* __restrict__ Cv, int ldc, int Nc,
    int K,
    size_t cSlice)
{
    extern __shared__ char smem_c[];
    const uint32_t sbase = smem_u32(smem_c);
    const int tid  = threadIdx.x;
    const int wid  = tid >> 5;
    const int lane = tid & 31;
    const int g    = lane >> 2;
    const int t4   = lane & 3;
    const int wm   = wid >> 2;
    const int wn   = wid & 3;
    const int mW   = wm * 64;
    const int nW   = wn * 32;
    const int m0 = blockIdx.y * 128;
    const int n0 = blockIdx.x * 128;
    const int kBase = blockIdx.z * K;
    const int iters = K / 64;

    const size_t zoff = (size_t)blockIdx.z * cSlice;
    const int ldw = K * gridDim.z;

    const uint32_t offA = (uint32_t)((mW + (lane & 15)) * ROWB + (lane >> 4) * 16);
    const uint32_t offB = (uint32_t)((nW + (lane & 15)) * ROWB + (lane >> 4) * 16);

    float acc[4][4][4];
    #pragma unroll
    for (int i = 0; i < 4; i++)
        #pragma unroll
        for (int j = 0; j < 4; j++)
            #pragma unroll
            for (int q = 0; q < 4; q++) acc[i][j][q] = 0.0f;

    stage_tile(sbase, sbase + TILE_B, A, lda, W, ldw, Nw, m0, n0, kBase, tid);
    cp_commit();
    {
        int k1 = (iters > 1) ? kBase + 64 : kBase;
        stage_tile(sbase + STAGE_B, sbase + STAGE_B + TILE_B,
                   A, lda, W, ldw, Nw, m0, n0, k1, tid);
    }
    cp_commit();

    for (int it = 0; it < iters; it++) {
        cp_wait<1>();
        __syncthreads();

        if (it + 2 < iters) {
            int s = (it + 2) % 3;
            stage_tile(sbase + (uint32_t)s * STAGE_B,
                       sbase + (uint32_t)s * STAGE_B + TILE_B,
                       A, lda, W, ldw, Nw, m0, n0, kBase + (it + 2) * 64, tid);
        }
        cp_commit();

        const uint32_t aBase = sbase + (uint32_t)(it % 3) * STAGE_B;
        const uint32_t bBase = aBase + TILE_B;

        #pragma unroll
        for (int ks = 0; ks < 4; ks++) {
            uint32_t b0r[4], b1r[4];
            ldsm_x4(b0r[0], b0r[1], b0r[2], b0r[3], bBase + offB + ks * 32);
            ldsm_x4(b1r[0], b1r[1], b1r[2], b1r[3],
                    bBase + offB + 16 * ROWB + ks * 32);
            #pragma unroll
            for (int i = 0; i < 4; i++) {
                uint32_t a0, a1, a2, a3;
                ldsm_x4(a0, a1, a2, a3,
                        aBase + offA + (uint32_t)(i * 16 * ROWB) + ks * 32);
                mma_f16(acc[i][0][0], acc[i][0][1], acc[i][0][2], acc[i][0][3],
                        a0, a1, a2, a3, b0r[0], b0r[2]);
                mma_f16(acc[i][1][0], acc[i][1][1], acc[i][1][2], acc[i][1][3],
                        a0, a1, a2, a3, b0r[1], b0r[3]);
                mma_f16(acc[i][2][0], acc[i][2][1], acc[i][2][2], acc[i][2][3],
                        a0, a1, a2, a3, b1r[0], b1r[2]);
                mma_f16(acc[i][3][0], acc[i][3][1], acc[i][3][2], acc[i][3][3],
                        a0, a1, a2, a3, b1r[1], b1r[3]);
            }
        }
    }

    #pragma unroll
    for (int i = 0; i < 4; i++) {
        #pragma unroll
        for (int j = 0; j < 4; j++) {
            int col = n0 + nW + j * 8 + t4 * 2;
            if (col < Nc) {
                int row0 = m0 + mW + i * 16 + g;
                float2 v0 = make_float2(acc[i][j][0], acc[i][j][1]);
                float2 v1 = make_float2(acc[i][j][2], acc[i][j][3]);
                if (EPI == 1) {
                    v0.x = softplusf(v0.x + bias[col]);
                    v0.y = softplusf(v0.y + bias[col + 1]);
                    v1.x = softplusf(v1.x + bias[col]);
                    v1.y = softplusf(v1.y + bias[col + 1]);
                }
                if (HOUT) {
                    __half* Ch = (__half*)Cv + zoff;
                    *(uint32_t*)&Ch[(size_t)row0 * ldc + col] = pack_h2(v0.x, v0.y);
                    *(uint32_t*)&Ch[(size_t)(row0 + 8) * ldc + col] = pack_h2(v1.x, v1.y);
                } else {
                    float* Cf = (float*)Cv + zoff;
                    *(float2*)&Cf[(size_t)row0 * ldc + col]       = v0;
                    *(float2*)&Cf[(size_t)(row0 + 8) * ldc + col] = v1;
                }
            }
        }
    }
}

// ---------------- split-K partial reduce ------------------------------------
__global__ __launch_bounds__(256) void reduce_splits_kernel(
    const float* __restrict__ part, float* __restrict__ out,
    __half* __restrict__ dtlow, int n4)
{
    int i = blockIdx.x * blockDim.x + threadIdx.x;
    if (i >= n4) return;
    const float4* p = (const float4*)part;
    float4 s = p[i];
    #pragma unroll
    for (int k = 1; k < XP_SPLITS; k++) {
        float4 v = p[(size_t)k * n4 + i];
        s.x += v.x; s.y += v.y; s.z += v.z; s.w += v.w;
    }
    int cq = i % (NDBL / 4);
    if (cq < (DTRANK / 4)) {
        int row = i / (NDBL / 4);
        *(uint2*)&dtlow[(size_t)row * DTRANK + cq * 4] =
            make_uint2(pack_h2(s.x, s.y), pack_h2(s.z, s.w));
    } else {
        ((float4*)out)[i] = s;
    }
}

// ------- 1) add + rmsnorm -> fp16 -------------------------------------------
__global__ __launch_bounds__(256) void addnorm_kernel(
    const float* __restrict__ hs,
    const float* __restrict__ res,
    const float* __restrict__ w,
    __half* __restrict__ out)
{
    int row = blockIdx.x;
    int tid = threadIdx.x;
    const float4* a4 = (const float4*)(hs  + (size_t)row * DMODEL);
    const float4* b4 = (const float4*)(res + (size_t)row * DMODEL);
    const float4* w4 = (const float4*)w;
    float4 v = a4[tid];
    float4 b = b4[tid];
    v.x += b.x; v.y += b.y; v.z += b.z; v.w += b.w;
    float ss = v.x*v.x + v.y*v.y + v.z*v.z + v.w*v.w;

    __shared__ float red[8];
    #pragma unroll
    for (int off = 16; off > 0; off >>= 1)
        ss += __shfl_xor_sync(0xffffffffu, ss, off);
    if ((tid & 31) == 0) red[tid >> 5] = ss;
    __syncthreads();
    if (tid < 32) {
        float s = (tid < 8) ? red[tid] : 0.0f;
        #pragma unroll
        for (int off = 4; off > 0; off >>= 1)
            s += __shfl_xor_sync(0xffffffffu, s, off);
        if (tid == 0) red[0] = s;
    }
    __syncthreads();
    float rstd = rsqrtf(red[0] * (1.0f / DMODEL) + 1e-5f);

    float4 ww = w4[tid];
    *(uint2*)&out[(size_t)row * DMODEL + tid * 4] =
        make_uint2(pack_h2(v.x * rstd * ww.x, v.y * rstd * ww.y),
                   pack_h2(v.z * rstd * ww.z, v.w * rstd * ww.w));
}

// ------- 3) causal depthwise conv + bias + SiLU -> fp16 only ----------------
__global__ __launch_bounds__(256) void conv_silu_kernel(
    const __half* __restrict__ xz,
    const float* __restrict__ cw,
    const float* __restrict__ cb,
    __half* __restrict__ xch)
{
    int idx = blockIdx.x * blockDim.x + threadIdx.x;
    int dq = idx & (DINNER / 4 - 1);
    int tq = idx / (DINNER / 4);
    int d  = dq * 4;
    int t0 = tq * 4;
    int l0 = t0 & (LSEQ - 1);

    float4 bias4 = *(const float4*)&cb[d];
    float4 w0 = *(const float4*)&cw[(d + 0) * 4];
    float4 w1 = *(const float4*)&cw[(d + 1) * 4];
    float4 w2 = *(const float4*)&cw[(d + 2) * 4];
    float4 w3 = *(const float4*)&cw[(d + 3) * 4];
    float wv0[4] = {w0.x, w0.y, w0.z, w0.w};
    float wv1[4] = {w1.x, w1.y, w1.z, w1.w};
    float wv2[4] = {w2.x, w2.y, w2.z, w2.w};
    float wv3[4] = {w3.x, w3.y, w3.z, w3.w};

    float4 v[7];
    #pragma unroll
    for (int k = 0; k < 7; k++) {
        if (l0 == 0 && k < 3) {
            v[k] = make_float4(0.f, 0.f, 0.f, 0.f);
        } else {
            uint2 u = *(const uint2*)&xz[(size_t)(t0 - 3 + k) * (2 * DINNER) + d];
            float2 lo = unpack_h2(u.x);
            float2 hi = unpack_h2(u.y);
            v[k] = make_float4(lo.x, lo.y, hi.x, hi.y);
        }
    }

    #pragma unroll
    for (int r = 0; r < 4; r++) {
        float a0 = bias4.x, a1 = bias4.y, a2 = bias4.z, a3 = bias4.w;
        #pragma unroll
        for (int j = 0; j < 4; j++) {
            float4 u = v[r + j];
            a0 = fmaf(u.x, wv0[j], a0);
            a1 = fmaf(u.y, wv1[j], a1);
            a2 = fmaf(u.z, wv2[j], a2);
            a3 = fmaf(u.w, wv3[j], a3);
        }
        size_t t = (size_t)(t0 + r);
        *(uint2*)&xch[t * DINNER + d] =
            make_uint2(pack_h2(siluf(a0), siluf(a1)),
                       pack_h2(siluf(a2), siluf(a3)));
    }
}

// ------- 4a) scan pass 1: per-chunk q (scan from 0) and P = exp(A*sum_dt) ---
// grid: (BATCH*128*NCHUNK) blocks of 256. block -> (b, dgroup, chunk).
__global__ __launch_bounds__(256) void scan_pass1_kernel(
    const __half* __restrict__ dt,
    const __half* __restrict__ xch,
    const float* __restrict__ xdbl,
    const float* __restrict__ A_log,
    float* __restrict__ qout,
    float* __restrict__ pout)
{
    const int CH = 64;
    __shared__ float sdt[CH][16], sx[CH][16], sB[CH][16];

    int bi = blockIdx.x;
    int ck = bi & (NCHUNK - 1);
    int bd = bi >> 3;                 // b*128 + dgroup
    int dg = bd & 127;
    int b  = bd >> 7;
    int d0 = dg * 16;
    int tid = threadIdx.x;
    int c = tid >> 4;
    int n = tid & 15;
    int d = d0 + c;

    float Acoef = -expf(A_log[d * DSTATE + n]);
    float h = 0.0f;
    float S = 0.0f;

    int e  = tid * 4;
    int le = e >> 4;
    int ie = e & 15;
    int tBase = ck * CLEN;

    for (int l0 = 0; l0 < CLEN; l0 += CH) {
        {
            size_t t = (size_t)b * LSEQ + tBase + l0 + le;
            uint2 ud = *(const uint2*)&dt[t * DINNER + d0 + ie];
            float2 dlo = unpack_h2(ud.x), dhi = unpack_h2(ud.y);
            *(float4*)&sdt[le][ie] = make_float4(dlo.x, dlo.y, dhi.x, dhi.y);
            uint2 ux = *(const uint2*)&xch[t * DINNER + d0 + ie];
            float2 xlo = unpack_h2(ux.x), xhi = unpack_h2(ux.y);
            *(float4*)&sx [le][ie] = make_float4(xlo.x, xlo.y, xhi.x, xhi.y);
            *(float4*)&sB [le][ie] = *(const float4*)&xdbl[t * NDBL + DTRANK + ie];
        }
        __syncthreads();

        #pragma unroll 4
        for (int ll = 0; ll < CH; ll++) {
            float dtv = sdt[ll][c];
            float xv  = sx[ll][c];
            float ea  = __expf(dtv * Acoef);
            h = fmaf(ea, h, dtv * xv * sB[ll][n]);
            S += dtv;
        }
        __syncthreads();
    }

    int gidx = bi * 256 + tid;
    qout[gidx] = h;
    pout[gidx] = __expf(S * Acoef);
}

// ------- 4b) chunk prefix: H_in per chunk (exclusive scan over chunks) ------
__global__ __launch_bounds__(256) void scan_mid_kernel(
    const float* __restrict__ q,
    const float* __restrict__ P,
    float* __restrict__ Hpref)
{
    int idx = blockIdx.x * blockDim.x + threadIdx.x;   // 0 .. BATCH*128*256-1
    int lane = idx & 255;
    int bd   = idx >> 8;
    float H = 0.0f;
    #pragma unroll
    for (int c = 0; c < NCHUNK; c++) {
        int off = (bd * NCHUNK + c) * 256 + lane;
        Hpref[off] = H;
        H = fmaf(P[off], H, q[off]);
    }
}

// ------- 4c) scan pass 2: seeded scan, emits y -------------------------------
__global__ __launch_bounds__(256) void scan_pass2_kernel(
    const __half* __restrict__ dt,
    const __half* __restrict__ xz,
    const __half* __restrict__ xch,
    const float* __restrict__ xdbl,
    const float* __restrict__ A_log,
    const float* __restrict__ Dp,
    const float* __restrict__ Hpref,
    __half* __restrict__ y)
{
    const int CH = 64;
    __shared__ float sdt[CH][16], sx[CH][16], sz[CH][16];
    __shared__ float sB[CH][16], sC[CH][16], sy[CH][16];

    int bi = blockIdx.x;
    int ck = bi & (NCHUNK - 1);
    int bd = bi >> 3;
    int dg = bd & 127;
    int b  = bd >> 7;
    int d0 = dg * 16;
    int tid = threadIdx.x;
    int c = tid >> 4;
    int n = tid & 15;
    int d = d0 + c;

    float Acoef = -expf(A_log[d * DSTATE + n]);
    float h = Hpref[bi * 256 + tid];

    int e  = tid * 4;
    int le = e >> 4;
    int ie = e & 15;
    int tBase = ck * CLEN;

    for (int l0 = 0; l0 < CLEN; l0 += CH) {
        {
            size_t t = (size_t)b * LSEQ + tBase + l0 + le;
            uint2 ud = *(const uint2*)&dt[t * DINNER + d0 + ie];
            float2 dlo = unpack_h2(ud.x), dhi = unpack_h2(ud.y);
            *(float4*)&sdt[le][ie] = make_float4(dlo.x, dlo.y, dhi.x, dhi.y);
            uint2 ux = *(const uint2*)&xch[t * DINNER + d0 + ie];
            float2 xlo = unpack_h2(ux.x), xhi = unpack_h2(ux.y);
            *(float4*)&sx [le][ie] = make_float4(xlo.x, xlo.y, xhi.x, xhi.y);
            uint2 uz = *(const uint2*)&xz[t * (2 * DINNER) + DINNER + d0 + ie];
            float2 zlo = unpack_h2(uz.x), zhi = unpack_h2(uz.y);
            *(float4*)&sz [le][ie] = make_float4(zlo.x, zlo.y, zhi.x, zhi.y);
            *(float4*)&sB [le][ie] = *(const float4*)&xdbl[t * NDBL + DTRANK + ie];
            *(float4*)&sC [le][ie] = *(const float4*)&xdbl[t * NDBL + DTRANK + DSTATE + ie];
        }
        __syncthreads();

        #pragma unroll 4
        for (int ll = 0; ll < CH; ll++) {
            float dtv = sdt[ll][c];
            float xv  = sx[ll][c];
            float ea  = __expf(dtv * Acoef);
            h = fmaf(ea, h, dtv * xv * sB[ll][n]);
            float p = h * sC[ll][n];
            p += __shfl_xor_sync(0xffffffffu, p, 8);
            p += __shfl_xor_sync(0xffffffffu, p, 4);
            p += __shfl_xor_sync(0xffffffffu, p, 2);
            p += __shfl_xor_sync(0xffffffffu, p, 1);
            if (n == 0) sy[ll][c] = p;
        }
        __syncthreads();

        {
            size_t t = (size_t)b * LSEQ + tBase + l0 + le;
            float4 ys = *(float4*)&sy[le][ie];
            float4 xs = *(float4*)&sx[le][ie];
            float4 zs = *(float4*)&sz[le][ie];
            float4 dd = *(const float4*)&Dp[d0 + ie];
            float o0 = (ys.x + xs.x * dd.x) * siluf(zs.x);
            float o1 = (ys.y + xs.y * dd.y) * siluf(zs.y);
            float o2 = (ys.z + xs.z * dd.z) * siluf(zs.z);
            float o3 = (ys.w + xs.w * dd.w) * siluf(zs.w);
            *(uint2*)&y[t * DINNER + d0 + ie] =
                make_uint2(pack_h2(o0, o1), pack_h2(o2, o3));
        }
        __syncthreads();
    }
}

// ---------------- launcher ----------------
extern "C" void kernel_launch(void* const* d_in, const int* in_sizes, int n_in,
                              void* d_out, int out_size)
{
    (void)in_sizes; (void)n_in; (void)out_size;
    const float* hs        = (const float*)d_in[1];
    const float* residual  = (const float*)d_in[2];
    const float* norm_w    = (const float*)d_in[3];
    const float* in_proj_w = (const float*)d_in[4];
    const float* conv_w    = (const float*)d_in[5];
    const float* conv_b    = (const float*)d_in[6];
    const float* x_proj_w  = (const float*)d_in[7];
    const float* dt_proj_w = (const float*)d_in[8];
    const float* dt_proj_b = (const float*)d_in[9];
    const float* A_log     = (const float*)d_in[10];
    const float* D_param   = (const float*)d_in[11];
    const float* out_proj_w= (const float*)d_in[12];
    float* out = (float*)d_out;

    static float* scratch = nullptr;
    if (!scratch) {
        void* p = nullptr;
        cudaGetSymbolAddress(&p, g_scratch);
        scratch = (float*)p;
        cudaFuncSetAttribute(mm_f16<0, false>, cudaFuncAttributeMaxDynamicSharedMemorySize, MM_SMEM_BYTES);
        cudaFuncSetAttribute(mm_f16<0, true>,  cudaFuncAttributeMaxDynamicSharedMemorySize, MM_SMEM_BYTES);
        cudaFuncSetAttribute(mm_f16<1, true>,  cudaFuncAttributeMaxDynamicSharedMemorySize, MM_SMEM_BYTES);
    }
    float*  g_xdbl = scratch + OFF_XDBL;
    float*  g_xp   = scratch + OFF_XP;
    float*  g_q    = scratch + OFF_Q;
    float*  g_p    = scratch + OFF_P;
    float*  g_hp   = scratch + OFF_HP;
    __half* g_xzh  = (__half*)(scratch + OFF_XZH);
    __half* g_h2   = (__half*)(scratch + OFF_H2);
    __half* g_xch  = (__half*)(scratch + OFF_XCH);
    __half* g_dtl  = (__half*)(scratch + OFF_DTL);
    __half* g_dth  = (__half*)(scratch + OFF_DTH);
    __half* g_y2   = (__half*)(scratch + OFF_Y2);
    __half* g_win  = (__half*)(scratch + OFF_WIN2);
    __half* g_wxp  = (__half*)(scratch + OFF_WXP2);
    __half* g_wdt  = (__half*)(scratch + OFF_WDT2);
    __half* g_wop  = (__half*)(scratch + OFF_WOP2);

    // 0) all weights fp32 -> fp16 in one launch
    w2h_all_kernel<<<(S_ALL + 255) / 256, 256>>>(
        (const float4*)in_proj_w, (const float4*)x_proj_w,
        (const float4*)dt_proj_w, (const float4*)out_proj_w,
        (uint2*)g_win, (uint2*)g_wxp, (uint2*)g_wdt, (uint2*)g_wop);

    // 1) h = fp16(rmsnorm(hidden + residual) * w)
    addnorm_kernel<<<NTOK, 256>>>(hs, residual, norm_w, g_h2);

    // 2) xz = h @ in_proj_w^T   [4096 x 4096], K=1024, fp16 output
    mm_f16<0, true><<<dim3(4096 / 128, NTOK / 128, 1), 256, MM_SMEM_BYTES>>>(
        g_h2, DMODEL, g_win, 2 * DINNER, nullptr,
        g_xzh, 2 * DINNER, 2 * DINNER, DMODEL, 0);

    // 3) xc = silu(causal_conv(x) + b)  -> fp16
    conv_silu_kernel<<<(NTOK / 4) * (DINNER / 4) / 256, 256>>>(
        g_xzh, conv_w, conv_b, g_xch);

    // 4) x_dbl partials = xc @ x_proj_w^T   [4096 x 96], K=2048, split-K=8
    mm_f16<0, false><<<dim3(1, NTOK / 128, XP_SPLITS), 256, MM_SMEM_BYTES>>>(
        g_xch, DINNER, g_wxp, NDBL, nullptr,
        g_xp, NDBL, NDBL, DINNER / XP_SPLITS, (size_t)NTOK * NDBL);
    reduce_splits_kernel<<<(NTOK * NDBL / 4 + 255) / 256, 256>>>(
        g_xp, g_xdbl, g_dtl, NTOK * NDBL / 4);

    // 5) dt = softplus(dtlow @ dt_proj_w^T + b)   [4096 x 2048], K=64, fp16 out
    mm_f16<1, true><<<dim3(DINNER / 128, NTOK / 128, 1), 256, MM_SMEM_BYTES>>>(
        g_dtl, DTRANK, g_wdt, DINNER, dt_proj_b,
        g_dth, DINNER, DINNER, DTRANK, 0);

    // 6) chunked selective scan (pass1 -> chunk prefix -> pass2)
    scan_pass1_kernel<<<BATCH * 128 * NCHUNK, 256>>>(
        g_dth, g_xch, g_xdbl, A_log, g_q, g_p);
    scan_mid_kernel<<<(BATCH * 128 * 256) / 256, 256>>>(g_q, g_p, g_hp);
    scan_pass2_kernel<<<BATCH * 128 * NCHUNK, 256>>>(
        g_dth, g_xzh, g_xch, g_xdbl, A_log, D_param, g_hp, g_y2);

    // 7) out = y @ out_proj_w^T   [4096 x 1024], K=2048
    mm_f16<0, false><<<dim3(DMODEL / 128, NTOK / 128, 1), 256, MM_SMEM_BYTES>>>(
        g_y2, DINNER, g_wop, DMODEL, nullptr,
        out, DMODEL, DMODEL, DINNER, 0);
}